// round 10
// baseline (speedup 1.0000x reference)
#include <cuda_runtime.h>
#include <cuda_bf16.h>
#include <math.h>
#include <stdint.h>

#define NH     16
#define NKV    4
#define HDIM   128
#define BATCH  2
#define SEQ    2048
#define DMODEL 2048
#define NTOK   (BATCH*SEQ)

// ---------------------------------------------------------------------------
// scratch (static __device__, no cudaMalloc)
// ---------------------------------------------------------------------------
static __device__ float g_q[NTOK * NH * HDIM];
static __device__ float g_k[NTOK * NKV * HDIM];
static __device__ float g_v[NTOK * NKV * HDIM];
static __device__ float g_ctx[NTOK * DMODEL];

static __device__ unsigned g_amax[10]; // 0:x 1:wq 2:wk 3:wv 4:wo 5:v 6:ctx 7:q 8:k

static __device__ signed char g_x1[NTOK * DMODEL],  g_x0[NTOK * DMODEL];
static __device__ signed char g_ct1[NTOK * DMODEL], g_ct0[NTOK * DMODEL];
static __device__ signed char g_wq1[DMODEL * DMODEL], g_wq0[DMODEL * DMODEL];
static __device__ signed char g_wk1[DMODEL * 512],    g_wk0[DMODEL * 512];
static __device__ signed char g_wv1[DMODEL * 512],    g_wv0[DMODEL * 512];
static __device__ signed char g_wo1[DMODEL * DMODEL], g_wo0[DMODEL * DMODEL];
static __device__ signed char g_q1[NTOK * NH * HDIM], g_q0[NTOK * NH * HDIM];
static __device__ signed char g_k1[NTOK * NKV * HDIM], g_k0[NTOK * NKV * HDIM];
static __device__ signed char g_vt1[BATCH * NKV * HDIM * SEQ], g_vt0[BATCH * NKV * HDIM * SEQ];

#define QMAX 32256.0f

// ---------------------------------------------------------------------------
// helpers
// ---------------------------------------------------------------------------
__device__ __forceinline__ uint32_t smem_u32(const void* p) {
  uint32_t a;
  asm("{ .reg .u64 t; cvta.to.shared.u64 t, %1; cvt.u32.u64 %0, t; }" : "=r"(a) : "l"(p));
  return a;
}

#define LDSM4(R, addr)                                                        \
  asm volatile("ldmatrix.sync.aligned.m8n8.x4.shared.b16 {%0,%1,%2,%3}, [%4];"\
    : "=r"((R)[0]), "=r"((R)[1]), "=r"((R)[2]), "=r"((R)[3]) : "r"(addr))

#define IMMA(D, A, b0v, b1v)                                                  \
  asm volatile("mma.sync.aligned.m16n8k32.row.col.s32.s8.s8.s32 "             \
    "{%0,%1,%2,%3}, {%4,%5,%6,%7}, {%8,%9}, {%0,%1,%2,%3};"                   \
    : "+r"((D)[0]), "+r"((D)[1]), "+r"((D)[2]), "+r"((D)[3])                  \
    : "r"((A)[0]), "r"((A)[1]), "r"((A)[2]), "r"((A)[3]), "r"(b0v), "r"(b1v))

#define CP_ASYNC16(dst, src) \
  asm volatile("cp.async.cg.shared.global [%0], [%1], 16;" :: "r"(dst), "l"(src))
#define CP_COMMIT() asm volatile("cp.async.commit_group;")

__device__ __forceinline__ void quant16(float v, float s, signed char& hi, signed char& lo) {
  int vi = __float2int_rn(v * s);
  vi = max(-32384, min(32384, vi));
  int h = (vi + 128) >> 8;
  hi = (signed char)h;
  lo = (signed char)(vi - (h << 8));
}

__device__ __forceinline__ float dig3(int h, int m, int l) {
  long long t = ((long long)h << 16) + ((long long)m << 8) + (long long)l;
  return (float)t;
}

// ---------------------------------------------------------------------------
// scale reduction + quantization kernels
// ---------------------------------------------------------------------------
__global__ void zero_amax_kernel() { if (threadIdx.x < 10) g_amax[threadIdx.x] = 0u; }

__global__ void __launch_bounds__(256) absmax_kernel(const float* __restrict__ p,
                                                     int n, int slot) {
  float m = 0.f;
  for (int i = blockIdx.x * 256 + threadIdx.x; i < n; i += gridDim.x * 256)
    m = fmaxf(m, fabsf(p[i]));
  #pragma unroll
  for (int o = 16; o; o >>= 1) m = fmaxf(m, __shfl_xor_sync(0xffffffffu, m, o));
  if ((threadIdx.x & 31) == 0) atomicMax(&g_amax[slot], __float_as_uint(m));
}

__global__ void __launch_bounds__(256) quant_kernel(const float* __restrict__ src,
    signed char* __restrict__ d1, signed char* __restrict__ d0, int n, int slot) {
  int i = blockIdx.x * 256 + threadIdx.x;
  if (i < n) {
    float s = QMAX / __uint_as_float(g_amax[slot]);
    signed char hi, lo;
    quant16(src[i], s, hi, lo);
    d1[i] = hi; d0[i] = lo;
  }
}

// W [K,N] fp32 -> transposed int8 digit planes [N,K]
__global__ void __launch_bounds__(256) wquant_kernel(const float* __restrict__ W,
    signed char* __restrict__ t1, signed char* __restrict__ t0,
    int K, int N, int slot) {
  __shared__ float t[32][33];
  int n0 = blockIdx.x * 32, k0 = blockIdx.y * 32;
  int x = threadIdx.x, y = threadIdx.y;
  #pragma unroll
  for (int i = 0; i < 4; i++)
    t[y * 4 + i][x] = W[(size_t)(k0 + y * 4 + i) * N + n0 + x];
  __syncthreads();
  float s = QMAX / __uint_as_float(g_amax[slot]);
  #pragma unroll
  for (int i = 0; i < 4; i++) {
    int n = n0 + y * 4 + i;
    signed char hi, lo;
    quant16(t[x][y * 4 + i], s, hi, lo);
    t1[(size_t)n * K + k0 + x] = hi;
    t0[(size_t)n * K + k0 + x] = lo;
  }
}

// V fp32 [tok, 512] -> transposed digit planes [b][hk][d][SEQ]
__global__ void __launch_bounds__(256) vtquant_kernel() {
  __shared__ float t[32][33];
  int t0i = blockIdx.x * 32, c0 = blockIdx.y * 32;
  int x = threadIdx.x, y = threadIdx.y;
  #pragma unroll
  for (int i = 0; i < 4; i++)
    t[y * 4 + i][x] = g_v[(size_t)(t0i + y * 4 + i) * (NKV * HDIM) + c0 + x];
  __syncthreads();
  float s = QMAX / __uint_as_float(g_amax[5]);
  #pragma unroll
  for (int i = 0; i < 4; i++) {
    int c = c0 + y * 4 + i;
    int tok = t0i + x;
    int b = tok >> 11, sidx = tok & (SEQ - 1);
    int hk = c >> 7, d = c & 127;
    signed char hi, lo;
    quant16(t[x][y * 4 + i], s, hi, lo);
    size_t o = (((size_t)(b * NKV + hk) * HDIM + d)) * SEQ + sidx;
    g_vt1[o] = hi; g_vt0[o] = lo;
  }
}

// ---------------------------------------------------------------------------
// int8 digit GEMM (4-term, digit-exact): C[M,N] = A[M,K] @ B^T.
// CTA 128x64, BK=64, 3-stage cp.async.
// ---------------------------------------------------------------------------
#define GI_RS 80
#define GI_A_BYTES (128 * GI_RS)
#define GI_B_BYTES (64 * GI_RS)
#define GI_STG (2 * GI_A_BYTES + 2 * GI_B_BYTES)
#define GI_SMEM (3 * GI_STG)

__global__ void __launch_bounds__(256, 2) gemm_i8_kernel(
    const signed char* __restrict__ A1, const signed char* __restrict__ A0,
    const signed char* __restrict__ B1, const signed char* __restrict__ B0,
    float* __restrict__ C, int K, int N, int slotA, int slotB) {
  extern __shared__ char smem[];
  uint32_t sb = smem_u32(smem);
  int tid = threadIdx.x, wid = tid >> 5, lane = tid & 31;
  int wm = wid >> 1, wn = wid & 1;
  int bm = blockIdx.y * 128, bn = blockIdx.x * 64;
  int nc = K / 64;

  auto load_chunk = [&](int c, int stg) {
    int k0 = c * 64;
    uint32_t base = sb + stg * GI_STG;
    #pragma unroll
    for (int i = 0; i < 2; i++) {
      int idx = tid + i * 256;
      int r = idx >> 2, g = idx & 3;
      CP_ASYNC16(base + r * GI_RS + g * 16,
                 A1 + (size_t)(bm + r) * K + k0 + g * 16);
      CP_ASYNC16(base + GI_A_BYTES + r * GI_RS + g * 16,
                 A0 + (size_t)(bm + r) * K + k0 + g * 16);
    }
    {
      int r = tid >> 2, g = tid & 3;
      CP_ASYNC16(base + 2 * GI_A_BYTES + r * GI_RS + g * 16,
                 B1 + (size_t)(bn + r) * K + k0 + g * 16);
      CP_ASYNC16(base + 2 * GI_A_BYTES + GI_B_BYTES + r * GI_RS + g * 16,
                 B0 + (size_t)(bn + r) * K + k0 + g * 16);
    }
    CP_COMMIT();
  };

  int accH[2][4][4], accM[2][4][4], accL[2][4][4];
  #pragma unroll
  for (int mi = 0; mi < 2; mi++)
    #pragma unroll
    for (int ni = 0; ni < 4; ni++)
      #pragma unroll
      for (int j = 0; j < 4; j++) {
        accH[mi][ni][j] = 0; accM[mi][ni][j] = 0; accL[mi][ni][j] = 0;
      }

  load_chunk(0, 0);
  load_chunk(1, 1);
  int lrow = lane & 15, lhi = lane >> 4;

  for (int c = 0; c < nc; c++) {
    asm volatile("cp.async.wait_group 1;");
    __syncthreads();
    if (c + 2 < nc) load_chunk(c + 2, (c + 2) % 3);
    else CP_COMMIT();

    uint32_t base = sb + (c % 3) * GI_STG;
    uint32_t a1s = base, a0s = base + GI_A_BYTES;
    uint32_t b1s = base + 2 * GI_A_BYTES, b0s = b1s + GI_B_BYTES;

    #pragma unroll
    for (int s = 0; s < 2; s++) {
      uint32_t koff = s * 32 + lhi * 16;
      uint32_t a1f[2][4], a0f[2][4], b1f[2][4], b0f[2][4];
      #pragma unroll
      for (int mi = 0; mi < 2; mi++) {
        uint32_t ao = (uint32_t)(wm * 32 + mi * 16 + lrow) * GI_RS + koff;
        LDSM4(a1f[mi], a1s + ao);
        LDSM4(a0f[mi], a0s + ao);
      }
      #pragma unroll
      for (int p = 0; p < 2; p++) {
        uint32_t bo = (uint32_t)(wn * 32 + p * 16 + lrow) * GI_RS + koff;
        LDSM4(b1f[p], b1s + bo);
        LDSM4(b0f[p], b0s + bo);
      }
      #pragma unroll
      for (int p = 0; p < 2; p++)
        #pragma unroll
        for (int mi = 0; mi < 2; mi++) {
          IMMA(accH[mi][2 * p],     a1f[mi], b1f[p][0], b1f[p][2]);
          IMMA(accH[mi][2 * p + 1], a1f[mi], b1f[p][1], b1f[p][3]);
        }
      #pragma unroll
      for (int p = 0; p < 2; p++)
        #pragma unroll
        for (int mi = 0; mi < 2; mi++) {
          IMMA(accM[mi][2 * p],     a1f[mi], b0f[p][0], b0f[p][2]);
          IMMA(accM[mi][2 * p + 1], a1f[mi], b0f[p][1], b0f[p][3]);
          IMMA(accM[mi][2 * p],     a0f[mi], b1f[p][0], b1f[p][2]);
          IMMA(accM[mi][2 * p + 1], a0f[mi], b1f[p][1], b1f[p][3]);
        }
      #pragma unroll
      for (int p = 0; p < 2; p++)
        #pragma unroll
        for (int mi = 0; mi < 2; mi++) {
          IMMA(accL[mi][2 * p],     a0f[mi], b0f[p][0], b0f[p][2]);
          IMMA(accL[mi][2 * p + 1], a0f[mi], b0f[p][1], b0f[p][3]);
        }
    }
  }

  float dq = __uint_as_float(g_amax[slotA]) * __uint_as_float(g_amax[slotB]) *
             (1.0f / (QMAX * QMAX));
  int gid = lane >> 2, cid = lane & 3;
  #pragma unroll
  for (int mi = 0; mi < 2; mi++)
    #pragma unroll
    for (int ni = 0; ni < 4; ni++) {
      int row = bm + wm * 32 + mi * 16 + gid;
      int col = bn + wn * 32 + ni * 8 + cid * 2;
      float v0 = dig3(accH[mi][ni][0], accM[mi][ni][0], accL[mi][ni][0]) * dq;
      float v1 = dig3(accH[mi][ni][1], accM[mi][ni][1], accL[mi][ni][1]) * dq;
      float v2 = dig3(accH[mi][ni][2], accM[mi][ni][2], accL[mi][ni][2]) * dq;
      float v3 = dig3(accH[mi][ni][3], accM[mi][ni][3], accL[mi][ni][3]) * dq;
      *(float2*)(C + (size_t)row * N + col) = make_float2(v0, v1);
      *(float2*)(C + (size_t)(row + 8) * N + col) = make_float2(v2, v3);
    }
}

// ---------------------------------------------------------------------------
// RoPE + L2 norm: fp32 in-place (quantization happens in a later pass)
// ---------------------------------------------------------------------------
__global__ void __launch_bounds__(64) rope_norm_kernel() {
  int tok = blockIdx.x;
  int r = blockIdx.y;
  size_t off = (r < NH) ? ((size_t)tok * NH + r) * HDIM
                        : ((size_t)tok * NKV + (r - NH)) * HDIM;
  float* base = (r < NH) ? g_q + off : g_k + off;
  int pos = tok & (SEQ - 1);
  int i = threadIdx.x;
  float t0 = base[2 * i], t1 = base[2 * i + 1];
  float inv = exp2f((float)(2 * i) * (-13.287712379549449f / 128.0f));
  float ang = (float)pos * inv;
  float sn, cs;
  sincosf(ang, &sn, &cs);
  float r0 = t0 * cs - t1 * sn;
  float r1 = t0 * sn + t1 * cs;
  float ss = r0 * r0 + r1 * r1;
  #pragma unroll
  for (int o = 16; o; o >>= 1) ss += __shfl_xor_sync(0xffffffffu, ss, o);
  __shared__ float part[2];
  if ((i & 31) == 0) part[i >> 5] = ss;
  __syncthreads();
  float sc = rsqrtf((part[0] + part[1]) * (1.0f / 128.0f) + 1e-6f);
  base[2 * i] = r0 * sc;
  base[2 * i + 1] = r1 * sc;
}

// ---------------------------------------------------------------------------
// int8 MMA attention: QK 4-term, AV 4-term (both digit-exact),
// e-max-scaled P, 1/Z folded into the epilogue per row.
// ---------------------------------------------------------------------------
#define SCW 2056
#define APAD 144
#define OFF_Q1 131584
#define OFF_Q0 (OFF_Q1 + 16*APAD)
#define OFF_K1 (OFF_Q0 + 16*APAD)
#define OFF_K0 (OFF_K1 + 128*APAD)
#define OFF_P1 (OFF_K0 + 128*APAD)
#define OFF_P0 (OFF_P1 + 16*APAD)
#define OFF_RED (OFF_P0 + 16*APAD)
#define ATTN_SMEM (OFF_RED + 128)

__global__ void __launch_bounds__(256, 1) attn_i8_kernel(
    float* __restrict__ attn_out, int write_attn) {
  extern __shared__ char smc[];
  float* s_scores = (float*)smc;
  float* s_red = (float*)(smc + OFF_RED);
  uint32_t sb = smem_u32(smc);

  int qb = gridDim.x - 1 - blockIdx.x;
  int h = blockIdx.y, b = blockIdx.z;
  int hk = h >> 2;
  int tid = threadIdx.x, w = tid >> 5, lane = tid & 31;
  int kend = qb * 16 + 16;
  const float QS = 0.08838834764831845f *
      __uint_as_float(g_amax[7]) * __uint_as_float(g_amax[8]) /
      (QMAX * QMAX);
  int lrow = lane & 15, lhi = lane >> 4;

  {
    int pl = tid >> 7, r = (tid >> 3) & 15, g = tid & 7;
    const signed char* src = (pl ? g_q0 : g_q1) +
        ((size_t)(b * SEQ + qb * 16 + r) * NH + h) * HDIM + g * 16;
    *(uint4*)(smc + (pl ? OFF_Q0 : OFF_Q1) + r * APAD + g * 16) = *(const uint4*)src;
  }
  __syncthreads();

  uint32_t q1f[4][4], q0f[4][4];
  #pragma unroll
  for (int s = 0; s < 4; s++) {
    uint32_t off = lrow * APAD + s * 32 + lhi * 16;
    LDSM4(q1f[s], sb + OFF_Q1 + off);
    LDSM4(q0f[s], sb + OFF_Q0 + off);
  }

  // ---- scores (4-term: exact digit arithmetic) ----
  for (int kc = 0; kc < kend; kc += 128) {
    __syncthreads();
    #pragma unroll
    for (int ii = 0; ii < 8; ii++) {
      int idx = tid + ii * 256;
      int pl = idx >> 10, j = (idx >> 3) & 127, g = idx & 7;
      uint4 v = {0, 0, 0, 0};
      if (kc + j < kend)
        v = *(const uint4*)((pl ? g_k0 : g_k1) +
            ((size_t)(b * SEQ + kc + j) * NKV + hk) * HDIM + g * 16);
      *(uint4*)(smc + (pl ? OFF_K0 : OFF_K1) + j * APAD + g * 16) = v;
    }
    __syncthreads();

    int aH[2][4] = {{0,0,0,0},{0,0,0,0}};
    int aM[2][4] = {{0,0,0,0},{0,0,0,0}};
    int aL[2][4] = {{0,0,0,0},{0,0,0,0}};
    int n0 = w * 16;
    #pragma unroll
    for (int s = 0; s < 4; s++) {
      uint32_t off = (uint32_t)(n0 + lrow) * APAD + s * 32 + lhi * 16;
      uint32_t kb1[4], kb0[4];
      LDSM4(kb1, sb + OFF_K1 + off);
      LDSM4(kb0, sb + OFF_K0 + off);
      IMMA(aH[0], q1f[s], kb1[0], kb1[2]);
      IMMA(aH[1], q1f[s], kb1[1], kb1[3]);
      IMMA(aM[0], q1f[s], kb0[0], kb0[2]);
      IMMA(aM[1], q1f[s], kb0[1], kb0[3]);
      IMMA(aL[0], q0f[s], kb0[0], kb0[2]);
      IMMA(aL[1], q0f[s], kb0[1], kb0[3]);
      IMMA(aM[0], q0f[s], kb1[0], kb1[2]);
      IMMA(aM[1], q0f[s], kb1[1], kb1[3]);
    }
    int r0 = lane >> 2, c0 = (lane & 3) * 2;
    int qs0 = qb * 16;
    #pragma unroll
    for (int nt = 0; nt < 2; nt++) {
      int col = kc + n0 + nt * 8 + c0;
      float e0 = dig3(aH[nt][0], aM[nt][0], aL[nt][0]) * QS;
      float e1 = dig3(aH[nt][1], aM[nt][1], aL[nt][1]) * QS;
      float e2 = dig3(aH[nt][2], aM[nt][2], aL[nt][2]) * QS;
      float e3 = dig3(aH[nt][3], aM[nt][3], aL[nt][3]) * QS;
      s_scores[r0 * SCW + col]           = (col     <= qs0 + r0)     ? e0 : -1e30f;
      s_scores[r0 * SCW + col + 1]       = (col + 1 <= qs0 + r0)     ? e1 : -1e30f;
      s_scores[(r0 + 8) * SCW + col]     = (col     <= qs0 + r0 + 8) ? e2 : -1e30f;
      s_scores[(r0 + 8) * SCW + col + 1] = (col + 1 <= qs0 + r0 + 8) ? e3 : -1e30f;
    }
  }
  __syncthreads();

  // ---- softmax stats ----
  {
    int qi = tid >> 4, r = tid & 15;
    float m = -1e30f;
    for (int j = r; j < kend; j += 16) m = fmaxf(m, s_scores[qi * SCW + j]);
    #pragma unroll
    for (int o = 8; o; o >>= 1) m = fmaxf(m, __shfl_xor_sync(0xffffffffu, m, o));
    float s = 0.f;
    for (int j = r; j < kend; j += 16) s += __expf(s_scores[qi * SCW + j] - m);
    #pragma unroll
    for (int o = 8; o; o >>= 1) s += __shfl_xor_sync(0xffffffffu, s, o);
    if (r == 0) { s_red[qi] = m; s_red[16 + qi] = 1.0f / s; }
  }
  __syncthreads();

  // ---- attn prob output ----
  if (write_attn) {
    float* ab = attn_out + ((size_t)(b * NH + h) * SEQ + (size_t)qb * 16) * SEQ;
    for (int idx = tid; idx < 16 * 512; idx += 256) {
      int qi = idx >> 9, j4 = (idx & 511) * 4;
      float m = s_red[qi], inv = s_red[16 + qi];
      float4 p = {0, 0, 0, 0};
      if (j4 < kend) {
        p.x = __expf(s_scores[qi * SCW + j4] - m) * inv;
        if (j4 + 1 < kend) p.y = __expf(s_scores[qi * SCW + j4 + 1] - m) * inv;
        if (j4 + 2 < kend) p.z = __expf(s_scores[qi * SCW + j4 + 2] - m) * inv;
        if (j4 + 3 < kend) p.w = __expf(s_scores[qi * SCW + j4 + 3] - m) * inv;
      }
      *(float4*)(ab + (size_t)qi * SEQ + j4) = p;
    }
  }

  // ---- AV (4-term, e-max-scaled P; 1/Z folded into epilogue) ----
  int oH[2][4] = {{0,0,0,0},{0,0,0,0}};
  int oM[2][4] = {{0,0,0,0},{0,0,0,0}};
  int oL[2][4] = {{0,0,0,0},{0,0,0,0}};
  for (int kc = 0; kc < kend; kc += 128) {
    __syncthreads();
    #pragma unroll
    for (int ii = 0; ii < 8; ii++) {
      int idx = tid + ii * 256;
      int pl = idx >> 10, d = (idx >> 3) & 127, g = idx & 7;
      uint4 v = {0, 0, 0, 0};
      if (kc + g * 16 < kend)
        v = *(const uint4*)((pl ? g_vt0 : g_vt1) +
            ((size_t)(b * NKV + hk) * HDIM + d) * SEQ + kc + g * 16);
      *(uint4*)(smc + (pl ? OFF_K0 : OFF_K1) + d * APAD + g * 16) = v;
    }
    // P digits in e-units (max = 1 exactly; no 1/Z here)
    for (int idx = tid; idx < 16 * 64; idx += 256) {
      int r = idx >> 6, c2 = (idx & 63) * 2;
      float m = s_red[r];
      float e0 = 0.f, e1 = 0.f;
      if (kc + c2 < kend)     e0 = __expf(s_scores[r * SCW + kc + c2] - m);
      if (kc + c2 + 1 < kend) e1 = __expf(s_scores[r * SCW + kc + c2 + 1] - m);
      signed char h0, l0, h1, l1;
      quant16(e0, QMAX, h0, l0);
      quant16(e1, QMAX, h1, l1);
      *(char2*)(smc + OFF_P1 + r * APAD + c2) = make_char2(h0, h1);
      *(char2*)(smc + OFF_P0 + r * APAD + c2) = make_char2(l0, l1);
    }
    __syncthreads();

    #pragma unroll
    for (int s = 0; s < 4; s++) {
      uint32_t pOff = lrow * APAD + s * 32 + lhi * 16;
      uint32_t p1f[4], p0f[4];
      LDSM4(p1f, sb + OFF_P1 + pOff);
      LDSM4(p0f, sb + OFF_P0 + pOff);
      uint32_t vOff = (uint32_t)(w * 16 + lrow) * APAD + s * 32 + lhi * 16;
      uint32_t vb1[4], vb0[4];
      LDSM4(vb1, sb + OFF_K1 + vOff);
      LDSM4(vb0, sb + OFF_K0 + vOff);
      IMMA(oH[0], p1f, vb1[0], vb1[2]);
      IMMA(oH[1], p1f, vb1[1], vb1[3]);
      IMMA(oM[0], p1f, vb0[0], vb0[2]);
      IMMA(oM[1], p1f, vb0[1], vb0[3]);
      IMMA(oL[0], p0f, vb0[0], vb0[2]);
      IMMA(oL[1], p0f, vb0[1], vb0[3]);
      IMMA(oM[0], p0f, vb1[0], vb1[2]);
      IMMA(oM[1], p0f, vb1[1], vb1[3]);
    }
  }

  // epilogue: fp32 ctx, per-row 1/Z
  {
    float avdq = __uint_as_float(g_amax[5]) * (1.0f / (QMAX * QMAX));
    int r0 = lane >> 2, c0 = (lane & 3) * 2;
    #pragma unroll
    for (int nt = 0; nt < 2; nt++) {
      int col = w * 16 + nt * 8 + c0;
      #pragma unroll
      for (int half = 0; half < 2; half++) {
        float inv = s_red[16 + r0 + half * 8];
        float v0 = dig3(oH[nt][2 * half], oM[nt][2 * half], oL[nt][2 * half]) * avdq * inv;
        float v1 = dig3(oH[nt][2 * half + 1], oM[nt][2 * half + 1], oL[nt][2 * half + 1]) * avdq * inv;
        size_t o = ((size_t)(b * SEQ + qb * 16 + r0 + half * 8)) * DMODEL + h * HDIM + col;
        *(float2*)(g_ctx + o) = make_float2(v0, v1);
      }
    }
  }
}

// ---------------------------------------------------------------------------
extern "C" void kernel_launch(void* const* d_in, const int* in_sizes, int n_in,
                              void* d_out, int out_size) {
  const float* x  = (const float*)d_in[0];
  const float* Wq = (const float*)d_in[1];
  const float* Wk = (const float*)d_in[2];
  const float* Wv = (const float*)d_in[3];
  const float* Wo = (const float*)d_in[4];
  float* out = (float*)d_out;
  float* attn = out + (size_t)NTOK * DMODEL;
  long long need = (long long)NTOK * DMODEL + (long long)BATCH * NH * SEQ * SEQ;
  int write_attn = ((long long)out_size >= need) ? 1 : 0;

  float *gq, *gk, *gv, *gctx;
  signed char *x1, *x0, *ct1, *ct0, *q1, *q0, *k1, *k0;
  signed char *wq1, *wq0, *wk1, *wk0, *wv1, *wv0, *wo1, *wo0;
  cudaGetSymbolAddress((void**)&gq, g_q);
  cudaGetSymbolAddress((void**)&gk, g_k);
  cudaGetSymbolAddress((void**)&gv, g_v);
  cudaGetSymbolAddress((void**)&gctx, g_ctx);
  cudaGetSymbolAddress((void**)&x1, g_x1);
  cudaGetSymbolAddress((void**)&x0, g_x0);
  cudaGetSymbolAddress((void**)&ct1, g_ct1);
  cudaGetSymbolAddress((void**)&ct0, g_ct0);
  cudaGetSymbolAddress((void**)&q1, g_q1);
  cudaGetSymbolAddress((void**)&q0, g_q0);
  cudaGetSymbolAddress((void**)&k1, g_k1);
  cudaGetSymbolAddress((void**)&k0, g_k0);
  cudaGetSymbolAddress((void**)&wq1, g_wq1);
  cudaGetSymbolAddress((void**)&wq0, g_wq0);
  cudaGetSymbolAddress((void**)&wk1, g_wk1);
  cudaGetSymbolAddress((void**)&wk0, g_wk0);
  cudaGetSymbolAddress((void**)&wv1, g_wv1);
  cudaGetSymbolAddress((void**)&wv0, g_wv0);
  cudaGetSymbolAddress((void**)&wo1, g_wo1);
  cudaGetSymbolAddress((void**)&wo0, g_wo0);

  cudaFuncSetAttribute(gemm_i8_kernel, cudaFuncAttributeMaxDynamicSharedMemorySize,
                       GI_SMEM);
  cudaFuncSetAttribute(attn_i8_kernel, cudaFuncAttributeMaxDynamicSharedMemorySize,
                       ATTN_SMEM);

  zero_amax_kernel<<<1, 32>>>();
  absmax_kernel<<<1024, 256>>>(x, NTOK * DMODEL, 0);
  absmax_kernel<<<1024, 256>>>(Wq, DMODEL * DMODEL, 1);
  absmax_kernel<<<512, 256>>>(Wk, DMODEL * 512, 2);
  absmax_kernel<<<512, 256>>>(Wv, DMODEL * 512, 3);
  absmax_kernel<<<1024, 256>>>(Wo, DMODEL * DMODEL, 4);

  quant_kernel<<<(NTOK * DMODEL + 255) / 256, 256>>>(x, x1, x0, NTOK * DMODEL, 0);
  wquant_kernel<<<dim3(DMODEL / 32, DMODEL / 32), dim3(32, 8)>>>(Wq, wq1, wq0, DMODEL, DMODEL, 1);
  wquant_kernel<<<dim3(512 / 32, DMODEL / 32), dim3(32, 8)>>>(Wk, wk1, wk0, DMODEL, 512, 2);
  wquant_kernel<<<dim3(512 / 32, DMODEL / 32), dim3(32, 8)>>>(Wv, wv1, wv0, DMODEL, 512, 3);
  wquant_kernel<<<dim3(DMODEL / 32, DMODEL / 32), dim3(32, 8)>>>(Wo, wo1, wo0, DMODEL, DMODEL, 4);

  gemm_i8_kernel<<<dim3(DMODEL / 64, NTOK / 128), 256, GI_SMEM>>>(
      x1, x0, wq1, wq0, gq, DMODEL, DMODEL, 0, 1);
  gemm_i8_kernel<<<dim3(512 / 64, NTOK / 128), 256, GI_SMEM>>>(
      x1, x0, wk1, wk0, gk, DMODEL, 512, 0, 2);
  gemm_i8_kernel<<<dim3(512 / 64, NTOK / 128), 256, GI_SMEM>>>(
      x1, x0, wv1, wv0, gv, DMODEL, 512, 0, 3);

  // RoPE + l2norm (fp32), then absmax-scaled quantization of q/k
  rope_norm_kernel<<<dim3(NTOK, NH + NKV), 64>>>();
  absmax_kernel<<<1024, 256>>>(gq, NTOK * NH * HDIM, 7);
  absmax_kernel<<<512, 256>>>(gk, NTOK * NKV * HDIM, 8);
  quant_kernel<<<(NTOK * NH * HDIM + 255) / 256, 256>>>(gq, q1, q0, NTOK * NH * HDIM, 7);
  quant_kernel<<<(NTOK * NKV * HDIM + 255) / 256, 256>>>(gk, k1, k0, NTOK * NKV * HDIM, 8);

  absmax_kernel<<<512, 256>>>(gv, NTOK * NKV * HDIM, 5);
  vtquant_kernel<<<dim3(NTOK / 32, (NKV * HDIM) / 32), dim3(32, 8)>>>();

  attn_i8_kernel<<<dim3(SEQ / 16, NH, BATCH), 256, ATTN_SMEM>>>(attn, write_attn);

  absmax_kernel<<<1024, 256>>>(gctx, NTOK * DMODEL, 6);
  quant_kernel<<<(NTOK * DMODEL + 255) / 256, 256>>>(gctx, ct1, ct0, NTOK * DMODEL, 6);
  gemm_i8_kernel<<<dim3(DMODEL / 64, NTOK / 128), 256, GI_SMEM>>>(
      ct1, ct0, wo1, wo0, out, DMODEL, DMODEL, 6, 4);
}

// round 11
// speedup vs baseline: 2.1007x; 2.1007x over previous
#include <cuda_runtime.h>
#include <cuda_bf16.h>
#include <math.h>
#include <stdint.h>

#define NH     16
#define NKV    4
#define HDIM   128
#define BATCH  2
#define SEQ    2048
#define DMODEL 2048
#define NTOK   (BATCH*SEQ)

// ---------------------------------------------------------------------------
// scratch
// ---------------------------------------------------------------------------
static __device__ float g_q[NTOK * NH * HDIM];
static __device__ float g_k[NTOK * NKV * HDIM];

static __device__ __nv_bfloat16 g_qh[NTOK * NH * HDIM];
static __device__ __nv_bfloat16 g_ql[NTOK * NH * HDIM];
static __device__ __nv_bfloat16 g_kbh[NTOK * NKV * HDIM];
static __device__ __nv_bfloat16 g_kbl[NTOK * NKV * HDIM];
static __device__ __nv_bfloat16 g_vbh[NTOK * NKV * HDIM];
static __device__ __nv_bfloat16 g_vbl[NTOK * NKV * HDIM];

static __device__ __nv_bfloat16 g_xh[NTOK * DMODEL];
static __device__ __nv_bfloat16 g_xl[NTOK * DMODEL];
static __device__ __nv_bfloat16 g_cth[NTOK * DMODEL];
static __device__ __nv_bfloat16 g_ctl[NTOK * DMODEL];
static __device__ __nv_bfloat16 g_wqh[DMODEL * (NH*HDIM)];
static __device__ __nv_bfloat16 g_wql[DMODEL * (NH*HDIM)];
static __device__ __nv_bfloat16 g_wkh[DMODEL * (NKV*HDIM)];
static __device__ __nv_bfloat16 g_wkl[DMODEL * (NKV*HDIM)];
static __device__ __nv_bfloat16 g_wvh[DMODEL * (NKV*HDIM)];
static __device__ __nv_bfloat16 g_wvl[DMODEL * (NKV*HDIM)];
static __device__ __nv_bfloat16 g_woh[DMODEL * DMODEL];
static __device__ __nv_bfloat16 g_wol[DMODEL * DMODEL];

// ---------------------------------------------------------------------------
// helpers
// ---------------------------------------------------------------------------
__device__ __forceinline__ uint32_t smem_u32(const void* p) {
  uint32_t a;
  asm("{ .reg .u64 t; cvta.to.shared.u64 t, %1; cvt.u32.u64 %0, t; }" : "=r"(a) : "l"(p));
  return a;
}

#define LDSM4(R, addr)                                                        \
  asm volatile("ldmatrix.sync.aligned.m8n8.x4.shared.b16 {%0,%1,%2,%3}, [%4];"\
    : "=r"((R)[0]), "=r"((R)[1]), "=r"((R)[2]), "=r"((R)[3]) : "r"(addr))

#define LDSM4T(R, addr)                                                       \
  asm volatile("ldmatrix.sync.aligned.m8n8.x4.trans.shared.b16 {%0,%1,%2,%3}, [%4];"\
    : "=r"((R)[0]), "=r"((R)[1]), "=r"((R)[2]), "=r"((R)[3]) : "r"(addr))

#define MMA16816(D, A, b0v, b1v)                                              \
  asm volatile("mma.sync.aligned.m16n8k16.row.col.f32.bf16.bf16.f32 "         \
    "{%0,%1,%2,%3}, {%4,%5,%6,%7}, {%8,%9}, {%0,%1,%2,%3};"                   \
    : "+f"((D)[0]), "+f"((D)[1]), "+f"((D)[2]), "+f"((D)[3])                  \
    : "r"((A)[0]), "r"((A)[1]), "r"((A)[2]), "r"((A)[3]), "r"(b0v), "r"(b1v))

#define CP_ASYNC16(dst, src) \
  asm volatile("cp.async.cg.shared.global [%0], [%1], 16;" :: "r"(dst), "l"(src))
#define CP_COMMIT() asm volatile("cp.async.commit_group;")

// ---------------------------------------------------------------------------
// split fp32 -> bf16 hi/lo
// ---------------------------------------------------------------------------
__global__ void __launch_bounds__(256) split_kernel(const float* __restrict__ src,
    __nv_bfloat16* __restrict__ hi, __nv_bfloat16* __restrict__ lo, int n) {
  int i = blockIdx.x * 256 + threadIdx.x;
  if (i < n) {
    float v = src[i];
    __nv_bfloat16 h = __float2bfloat16(v);
    hi[i] = h;
    lo[i] = __float2bfloat16(v - __bfloat162float(h));
  }
}

// W [K,N] fp32 -> transposed bf16 hi/lo [N,K]
__global__ void __launch_bounds__(256) wsplit_kernel(const float* __restrict__ W,
    __nv_bfloat16* __restrict__ th, __nv_bfloat16* __restrict__ tl, int K, int N) {
  __shared__ float t[32][33];
  int n0 = blockIdx.x * 32, k0 = blockIdx.y * 32;
  int x = threadIdx.x, y = threadIdx.y;  // 32 x 8
  #pragma unroll
  for (int i = 0; i < 4; i++)
    t[y * 4 + i][x] = W[(size_t)(k0 + y * 4 + i) * N + n0 + x];
  __syncthreads();
  #pragma unroll
  for (int i = 0; i < 4; i++) {
    int n = n0 + y * 4 + i;
    float v = t[x][y * 4 + i];
    __nv_bfloat16 h = __float2bfloat16(v);
    th[(size_t)n * K + k0 + x] = h;
    tl[(size_t)n * K + k0 + x] = __float2bfloat16(v - __bfloat162float(h));
  }
}

// ---------------------------------------------------------------------------
// mma.sync GEMM, bf16x3: C = A @ B^T (B stored [N,K]).
// 2-stage, 80KB smem, __launch_bounds__(256,2) -> 2 CTAs/SM (4 warps/SMSP).
// ---------------------------------------------------------------------------
#define GBM 128
#define GBN 128
#define GBK 32
#define RSTRIDE 80
#define TILE_BYTES (128 * RSTRIDE)     // 10240
#define STG_BYTES (4 * TILE_BYTES)     // 40960
#define GEMM_SMEM (2 * STG_BYTES)      // 81920

__global__ void __launch_bounds__(256, 2) gemm3_kernel(
    const __nv_bfloat16* __restrict__ Ah, const __nv_bfloat16* __restrict__ Al,
    const __nv_bfloat16* __restrict__ Bh, const __nv_bfloat16* __restrict__ Bl,
    float* __restrict__ Cf, __nv_bfloat16* __restrict__ Ch,
    __nv_bfloat16* __restrict__ Cl, int K, int N) {
  extern __shared__ char smem[];
  uint32_t sbase = smem_u32(smem);
  int tid = threadIdx.x;
  int wid = tid >> 5, lane = tid & 31;
  int wm = wid >> 1, wn = wid & 1;
  int bm = blockIdx.y * GBM, bn = blockIdx.x * GBN;
  int nc = K / GBK;

  const __nv_bfloat16* srcs[4] = {Ah, Al, Bh, Bl};
  int rbase[4] = {bm, bm, bn, bn};

  auto load_chunk = [&](int c, int buf) {
    int k0 = c * GBK;
    #pragma unroll
    for (int i = 0; i < 8; i++) {
      int idx = tid + i * 256;
      int t = i >> 1;
      int r = (idx >> 2) & 127;
      int g = idx & 3;
      uint32_t dst = sbase + buf * STG_BYTES + t * TILE_BYTES + r * RSTRIDE + g * 16;
      const __nv_bfloat16* src = srcs[t] + (size_t)(rbase[t] + r) * K + k0 + g * 8;
      CP_ASYNC16(dst, src);
    }
    CP_COMMIT();
  };

  float acc[2][8][4];
  #pragma unroll
  for (int mi = 0; mi < 2; mi++)
    #pragma unroll
    for (int ni = 0; ni < 8; ni++)
      #pragma unroll
      for (int j = 0; j < 4; j++) acc[mi][ni][j] = 0.f;

  load_chunk(0, 0);
  int lrow = lane & 15, lk8 = (lane >> 4) * 8;

  for (int c = 0; c < nc; c++) {
    if (c + 1 < nc) {
      load_chunk(c + 1, (c + 1) & 1);
      asm volatile("cp.async.wait_group 1;");
    } else {
      asm volatile("cp.async.wait_group 0;");
    }
    __syncthreads();

    uint32_t b0 = sbase + (c & 1) * STG_BYTES;
    uint32_t aHs = b0, aLs = b0 + TILE_BYTES;
    uint32_t bHs = b0 + 2 * TILE_BYTES, bLs = b0 + 3 * TILE_BYTES;

    #pragma unroll
    for (int kk = 0; kk < GBK; kk += 16) {
      uint32_t ah[2][4], al[2][4];
      uint32_t aoff = (uint32_t)(wm * 32 + lrow) * RSTRIDE + (kk + lk8) * 2;
      LDSM4(ah[0], aHs + aoff);
      LDSM4(ah[1], aHs + aoff + 16 * RSTRIDE);
      LDSM4(al[0], aLs + aoff);
      LDSM4(al[1], aLs + aoff + 16 * RSTRIDE);
      #pragma unroll
      for (int p = 0; p < 4; p++) {
        uint32_t boff = (uint32_t)(wn * 64 + p * 16 + lrow) * RSTRIDE + (kk + lk8) * 2;
        uint32_t h[4], l[4];
        LDSM4(h, bHs + boff);
        LDSM4(l, bLs + boff);
        #pragma unroll
        for (int mi = 0; mi < 2; mi++) {
          MMA16816(acc[mi][2 * p],     ah[mi], h[0], h[2]);
          MMA16816(acc[mi][2 * p + 1], ah[mi], h[1], h[3]);
          MMA16816(acc[mi][2 * p],     ah[mi], l[0], l[2]);
          MMA16816(acc[mi][2 * p + 1], ah[mi], l[1], l[3]);
          MMA16816(acc[mi][2 * p],     al[mi], h[0], h[2]);
          MMA16816(acc[mi][2 * p + 1], al[mi], h[1], h[3]);
        }
      }
    }
    __syncthreads();
  }

  int gid = lane >> 2, cid = lane & 3;
  if (Cf) {
    #pragma unroll
    for (int mi = 0; mi < 2; mi++)
      #pragma unroll
      for (int ni = 0; ni < 8; ni++) {
        int row = bm + wm * 32 + mi * 16 + gid;
        int col = bn + wn * 64 + ni * 8 + cid * 2;
        *(float2*)(Cf + (size_t)row * N + col) =
            make_float2(acc[mi][ni][0], acc[mi][ni][1]);
        *(float2*)(Cf + (size_t)(row + 8) * N + col) =
            make_float2(acc[mi][ni][2], acc[mi][ni][3]);
      }
  } else {
    #pragma unroll
    for (int mi = 0; mi < 2; mi++)
      #pragma unroll
      for (int ni = 0; ni < 8; ni++) {
        int row = bm + wm * 32 + mi * 16 + gid;
        int col = bn + wn * 64 + ni * 8 + cid * 2;
        #pragma unroll
        for (int half = 0; half < 2; half++) {
          float v0 = acc[mi][ni][2 * half], v1 = acc[mi][ni][2 * half + 1];
          __nv_bfloat16 h0 = __float2bfloat16(v0), h1 = __float2bfloat16(v1);
          __nv_bfloat162 hh; hh.x = h0; hh.y = h1;
          __nv_bfloat162 ll;
          ll.x = __float2bfloat16(v0 - __bfloat162float(h0));
          ll.y = __float2bfloat16(v1 - __bfloat162float(h1));
          size_t o = (size_t)(row + half * 8) * N + col;
          *(__nv_bfloat162*)(Ch + o) = hh;
          *(__nv_bfloat162*)(Cl + o) = ll;
        }
      }
  }
}

// ---------------------------------------------------------------------------
// RoPE + L2 norm: reads fp32 q/k, writes split bf16 only.
// ---------------------------------------------------------------------------
__global__ void __launch_bounds__(64) rope_norm_kernel() {
  int tok = blockIdx.x;
  int r = blockIdx.y;
  size_t off = (r < NH) ? ((size_t)tok * NH + r) * HDIM
                        : ((size_t)tok * NKV + (r - NH)) * HDIM;
  const float* base = (r < NH) ? g_q + off : g_k + off;
  __nv_bfloat16* bh = (r < NH) ? g_qh + off : g_kbh + off;
  __nv_bfloat16* bl = (r < NH) ? g_ql + off : g_kbl + off;
  int pos = tok & (SEQ - 1);
  int i = threadIdx.x;  // pair 0..63
  float t0 = base[2 * i], t1 = base[2 * i + 1];
  float inv = exp2f((float)(2 * i) * (-13.287712379549449f / 128.0f));
  float ang = (float)pos * inv;
  float sn, cs;
  sincosf(ang, &sn, &cs);
  float r0 = t0 * cs - t1 * sn;
  float r1 = t0 * sn + t1 * cs;
  float ss = r0 * r0 + r1 * r1;
  #pragma unroll
  for (int o = 16; o; o >>= 1) ss += __shfl_xor_sync(0xffffffffu, ss, o);
  __shared__ float part[2];
  if ((i & 31) == 0) part[i >> 5] = ss;
  __syncthreads();
  float sc = rsqrtf((part[0] + part[1]) * (1.0f / 128.0f) + 1e-6f);
  float v0 = r0 * sc, v1 = r1 * sc;
  __nv_bfloat16 h0 = __float2bfloat16(v0), h1 = __float2bfloat16(v1);
  bh[2 * i] = h0; bh[2 * i + 1] = h1;
  bl[2 * i] = __float2bfloat16(v0 - __bfloat162float(h0));
  bl[2 * i + 1] = __float2bfloat16(v1 - __bfloat162float(h1));
}

// ---------------------------------------------------------------------------
// MMA attention (R5 form), epilogue writes split bf16 ctx directly.
// ---------------------------------------------------------------------------
#define SCW 2056
#define PAD_STR 272
#define OFF_QH 131584
#define OFF_QL (OFF_QH + 16*PAD_STR)
#define OFF_KH (OFF_QL + 16*PAD_STR)
#define OFF_KL (OFF_KH + 128*PAD_STR)
#define OFF_PH (OFF_KL + 128*PAD_STR)
#define OFF_PL (OFF_PH + 16*PAD_STR)
#define OFF_RED (OFF_PL + 16*PAD_STR)
#define ATTN_SMEM (OFF_RED + 128)

__global__ void __launch_bounds__(256, 1) attn_mma_kernel(
    float* __restrict__ attn_out, int write_attn) {
  extern __shared__ char smc[];
  float* s_scores = (float*)smc;
  float* s_red = (float*)(smc + OFF_RED);
  uint32_t sb = smem_u32(smc);

  int qb = gridDim.x - 1 - blockIdx.x;
  int h = blockIdx.y, b = blockIdx.z;
  int hk = h >> 2;
  int tid = threadIdx.x, w = tid >> 5, lane = tid & 31;
  int kend = qb * 16 + 16;
  const float SC = 0.08838834764831845f;
  int lrow = lane & 15, lhi = lane >> 4;

  {
    int r = tid >> 4, g = tid & 15;
    size_t go = ((size_t)(b * SEQ + qb * 16 + r) * NH + h) * HDIM + g * 8;
    *(uint4*)(smc + OFF_QH + r * PAD_STR + g * 16) = *(const uint4*)(g_qh + go);
    *(uint4*)(smc + OFF_QL + r * PAD_STR + g * 16) = *(const uint4*)(g_ql + go);
  }
  __syncthreads();

  uint32_t aH[8][4], aL[8][4];
  #pragma unroll
  for (int kk = 0; kk < 8; kk++) {
    uint32_t off = lrow * PAD_STR + kk * 32 + lhi * 16;
    LDSM4(aH[kk], sb + OFF_QH + off);
    LDSM4(aL[kk], sb + OFF_QL + off);
  }

  // ---- scores ----
  for (int kc = 0; kc < kend; kc += 128) {
    __syncthreads();
    for (int idx = tid; idx < 128 * 16; idx += 256) {
      int j = idx >> 4, g = idx & 15;
      uint4 vh = {0, 0, 0, 0}, vl = {0, 0, 0, 0};
      if (kc + j < kend) {
        size_t go = ((size_t)(b * SEQ + kc + j) * NKV + hk) * HDIM + g * 8;
        vh = *(const uint4*)(g_kbh + go);
        vl = *(const uint4*)(g_kbl + go);
      }
      *(uint4*)(smc + OFF_KH + j * PAD_STR + g * 16) = vh;
      *(uint4*)(smc + OFF_KL + j * PAD_STR + g * 16) = vl;
    }
    __syncthreads();

    float acc[2][4] = {{0, 0, 0, 0}, {0, 0, 0, 0}};
    int n0 = w * 16;
    #pragma unroll
    for (int kk = 0; kk < 8; kk++) {
      uint32_t off = (n0 + lrow) * PAD_STR + kk * 32 + lhi * 16;
      uint32_t bh[4], bl[4];
      LDSM4(bh, sb + OFF_KH + off);
      LDSM4(bl, sb + OFF_KL + off);
      MMA16816(acc[0], aH[kk], bh[0], bh[2]);
      MMA16816(acc[1], aH[kk], bh[1], bh[3]);
      MMA16816(acc[0], aH[kk], bl[0], bl[2]);
      MMA16816(acc[1], aH[kk], bl[1], bl[3]);
      MMA16816(acc[0], aL[kk], bh[0], bh[2]);
      MMA16816(acc[1], aL[kk], bh[1], bh[3]);
    }
    int r0 = lane >> 2, c0 = (lane & 3) * 2;
    int qs0 = qb * 16;
    #pragma unroll
    for (int nt = 0; nt < 2; nt++) {
      int col = kc + n0 + nt * 8 + c0;
      s_scores[r0 * SCW + col]           = (col     <= qs0 + r0)     ? acc[nt][0] * SC : -1e30f;
      s_scores[r0 * SCW + col + 1]       = (col + 1 <= qs0 + r0)     ? acc[nt][1] * SC : -1e30f;
      s_scores[(r0 + 8) * SCW + col]     = (col     <= qs0 + r0 + 8) ? acc[nt][2] * SC : -1e30f;
      s_scores[(r0 + 8) * SCW + col + 1] = (col + 1 <= qs0 + r0 + 8) ? acc[nt][3] * SC : -1e30f;
    }
  }
  __syncthreads();

  // ---- softmax stats ----
  {
    int qi = tid >> 4, r = tid & 15;
    float m = -1e30f;
    for (int j = r; j < kend; j += 16) m = fmaxf(m, s_scores[qi * SCW + j]);
    #pragma unroll
    for (int o = 8; o; o >>= 1) m = fmaxf(m, __shfl_xor_sync(0xffffffffu, m, o));
    float s = 0.f;
    for (int j = r; j < kend; j += 16) s += __expf(s_scores[qi * SCW + j] - m);
    #pragma unroll
    for (int o = 8; o; o >>= 1) s += __shfl_xor_sync(0xffffffffu, s, o);
    if (r == 0) { s_red[qi] = m; s_red[16 + qi] = 1.0f / s; }
  }
  __syncthreads();

  // ---- attn prob output ----
  if (write_attn) {
    float* ab = attn_out + ((size_t)(b * NH + h) * SEQ + (size_t)qb * 16) * SEQ;
    for (int idx = tid; idx < 16 * 512; idx += 256) {
      int qi = idx >> 9, j4 = (idx & 511) * 4;
      float m = s_red[qi], inv = s_red[16 + qi];
      float4 p = {0, 0, 0, 0};
      if (j4 < kend) {
        p.x = __expf(s_scores[qi * SCW + j4] - m) * inv;
        if (j4 + 1 < kend) p.y = __expf(s_scores[qi * SCW + j4 + 1] - m) * inv;
        if (j4 + 2 < kend) p.z = __expf(s_scores[qi * SCW + j4 + 2] - m) * inv;
        if (j4 + 3 < kend) p.w = __expf(s_scores[qi * SCW + j4 + 3] - m) * inv;
      }
      *(float4*)(ab + (size_t)qi * SEQ + j4) = p;
    }
  }

  // ---- AV ----
  float oacc[2][4] = {{0, 0, 0, 0}, {0, 0, 0, 0}};
  for (int kc = 0; kc < kend; kc += 128) {
    __syncthreads();
    for (int idx = tid; idx < 128 * 16; idx += 256) {
      int j = idx >> 4, g = idx & 15;
      uint4 vh = {0, 0, 0, 0}, vl = {0, 0, 0, 0};
      if (kc + j < kend) {
        size_t go = ((size_t)(b * SEQ + kc + j) * NKV + hk) * HDIM + g * 8;
        vh = *(const uint4*)(g_vbh + go);
        vl = *(const uint4*)(g_vbl + go);
      }
      *(uint4*)(smc + OFF_KH + j * PAD_STR + g * 16) = vh;
      *(uint4*)(smc + OFF_KL + j * PAD_STR + g * 16) = vl;
    }
    for (int idx = tid; idx < 16 * 64; idx += 256) {
      int r = idx >> 6, c2 = (idx & 63) * 2;
      float m = s_red[r], inv = s_red[16 + r];
      float p0 = 0.f, p1 = 0.f;
      if (kc + c2 < kend)     p0 = __expf(s_scores[r * SCW + kc + c2] - m) * inv;
      if (kc + c2 + 1 < kend) p1 = __expf(s_scores[r * SCW + kc + c2 + 1] - m) * inv;
      __nv_bfloat16 h0 = __float2bfloat16(p0), h1 = __float2bfloat16(p1);
      __nv_bfloat162 hh; hh.x = h0; hh.y = h1;
      __nv_bfloat162 ll;
      ll.x = __float2bfloat16(p0 - __bfloat162float(h0));
      ll.y = __float2bfloat16(p1 - __bfloat162float(h1));
      *(__nv_bfloat162*)(smc + OFF_PH + r * PAD_STR + c2 * 2) = hh;
      *(__nv_bfloat162*)(smc + OFF_PL + r * PAD_STR + c2 * 2) = ll;
    }
    __syncthreads();

    #pragma unroll
    for (int kk = 0; kk < 8; kk++) {
      uint32_t pOff = lrow * PAD_STR + kk * 32 + lhi * 16;
      uint32_t ph[4], pl[4];
      LDSM4(ph, sb + OFF_PH + pOff);
      LDSM4(pl, sb + OFF_PL + pOff);
      uint32_t vOff = (kk * 16 + lrow) * PAD_STR + w * 32 + lhi * 16;
      uint32_t vh[4], vl[4];
      LDSM4T(vh, sb + OFF_KH + vOff);
      LDSM4T(vl, sb + OFF_KL + vOff);
      MMA16816(oacc[0], ph, vh[0], vh[1]);
      MMA16816(oacc[1], ph, vh[2], vh[3]);
      MMA16816(oacc[0], ph, vl[0], vl[1]);
      MMA16816(oacc[1], ph, vl[2], vl[3]);
      MMA16816(oacc[0], pl, vh[0], vh[1]);
      MMA16816(oacc[1], pl, vh[2], vh[3]);
    }
  }

  // epilogue: split ctx bf16 [tok, H*HD]
  {
    int r0 = lane >> 2, c0 = (lane & 3) * 2;
    #pragma unroll
    for (int nt = 0; nt < 2; nt++) {
      int col = w * 16 + nt * 8 + c0;
      #pragma unroll
      for (int half = 0; half < 2; half++) {
        float v0 = oacc[nt][2 * half], v1 = oacc[nt][2 * half + 1];
        __nv_bfloat16 h0 = __float2bfloat16(v0), h1 = __float2bfloat16(v1);
        __nv_bfloat162 hh; hh.x = h0; hh.y = h1;
        __nv_bfloat162 ll;
        ll.x = __float2bfloat16(v0 - __bfloat162float(h0));
        ll.y = __float2bfloat16(v1 - __bfloat162float(h1));
        size_t o = ((size_t)(b * SEQ + qb * 16 + r0 + half * 8)) * DMODEL
                 + h * HDIM + col;
        *(__nv_bfloat162*)(g_cth + o) = hh;
        *(__nv_bfloat162*)(g_ctl + o) = ll;
      }
    }
  }
}

// ---------------------------------------------------------------------------
extern "C" void kernel_launch(void* const* d_in, const int* in_sizes, int n_in,
                              void* d_out, int out_size) {
  const float* x  = (const float*)d_in[0];
  const float* Wq = (const float*)d_in[1];
  const float* Wk = (const float*)d_in[2];
  const float* Wv = (const float*)d_in[3];
  const float* Wo = (const float*)d_in[4];
  float* out = (float*)d_out;
  float* attn = out + (size_t)NTOK * DMODEL;
  long long need = (long long)NTOK * DMODEL + (long long)BATCH * NH * SEQ * SEQ;
  int write_attn = ((long long)out_size >= need) ? 1 : 0;

  float *gq, *gk;
  __nv_bfloat16 *xh, *xl, *cth, *ctl, *vbh, *vbl;
  __nv_bfloat16 *wqh, *wql, *wkh, *wkl, *wvh, *wvl, *woh, *wol;
  cudaGetSymbolAddress((void**)&gq, g_q);
  cudaGetSymbolAddress((void**)&gk, g_k);
  cudaGetSymbolAddress((void**)&xh, g_xh);
  cudaGetSymbolAddress((void**)&xl, g_xl);
  cudaGetSymbolAddress((void**)&cth, g_cth);
  cudaGetSymbolAddress((void**)&ctl, g_ctl);
  cudaGetSymbolAddress((void**)&vbh, g_vbh);
  cudaGetSymbolAddress((void**)&vbl, g_vbl);
  cudaGetSymbolAddress((void**)&wqh, g_wqh);
  cudaGetSymbolAddress((void**)&wql, g_wql);
  cudaGetSymbolAddress((void**)&wkh, g_wkh);
  cudaGetSymbolAddress((void**)&wkl, g_wkl);
  cudaGetSymbolAddress((void**)&wvh, g_wvh);
  cudaGetSymbolAddress((void**)&wvl, g_wvl);
  cudaGetSymbolAddress((void**)&woh, g_woh);
  cudaGetSymbolAddress((void**)&wol, g_wol);

  cudaFuncSetAttribute(gemm3_kernel, cudaFuncAttributeMaxDynamicSharedMemorySize,
                       GEMM_SMEM);
  cudaFuncSetAttribute(attn_mma_kernel, cudaFuncAttributeMaxDynamicSharedMemorySize,
                       ATTN_SMEM);

  {
    int n = NTOK * DMODEL;
    split_kernel<<<(n + 255) / 256, 256>>>(x, xh, xl, n);
  }
  wsplit_kernel<<<dim3((NH*HDIM)/32, DMODEL/32), dim3(32, 8)>>>(Wq, wqh, wql, DMODEL, NH*HDIM);
  wsplit_kernel<<<dim3((NKV*HDIM)/32, DMODEL/32), dim3(32, 8)>>>(Wk, wkh, wkl, DMODEL, NKV*HDIM);
  wsplit_kernel<<<dim3((NKV*HDIM)/32, DMODEL/32), dim3(32, 8)>>>(Wv, wvh, wvl, DMODEL, NKV*HDIM);
  wsplit_kernel<<<dim3(DMODEL/32, DMODEL/32), dim3(32, 8)>>>(Wo, woh, wol, DMODEL, DMODEL);

  gemm3_kernel<<<dim3((NH*HDIM)/GBN, NTOK/GBM), 256, GEMM_SMEM>>>(
      xh, xl, wqh, wql, gq, nullptr, nullptr, DMODEL, NH*HDIM);
  gemm3_kernel<<<dim3((NKV*HDIM)/GBN, NTOK/GBM), 256, GEMM_SMEM>>>(
      xh, xl, wkh, wkl, gk, nullptr, nullptr, DMODEL, NKV*HDIM);
  gemm3_kernel<<<dim3((NKV*HDIM)/GBN, NTOK/GBM), 256, GEMM_SMEM>>>(
      xh, xl, wvh, wvl, nullptr, vbh, vbl, DMODEL, NKV*HDIM);

  rope_norm_kernel<<<dim3(NTOK, NH + NKV), 64>>>();

  attn_mma_kernel<<<dim3(SEQ / 16, NH, BATCH), 256, ATTN_SMEM>>>(attn, write_attn);

  gemm3_kernel<<<dim3(DMODEL/GBN, NTOK/GBM), 256, GEMM_SMEM>>>(
      cth, ctl, woh, wol, out, nullptr, nullptr, DMODEL, DMODEL);
}

// round 12
// speedup vs baseline: 2.2822x; 1.0864x over previous
#include <cuda_runtime.h>
#include <cuda_fp16.h>
#include <math.h>
#include <stdint.h>

#define NH     16
#define NKV    4
#define HDIM   128
#define BATCH  2
#define SEQ    2048
#define DMODEL 2048
#define NTOK   (BATCH*SEQ)

// ---------------------------------------------------------------------------
// scratch
// ---------------------------------------------------------------------------
static __device__ float g_q[NTOK * NH * HDIM];
static __device__ float g_k[NTOK * NKV * HDIM];

static __device__ __half g_qh[NTOK * NH * HDIM];
static __device__ __half g_ql[NTOK * NH * HDIM];
static __device__ __half g_kbh[NTOK * NKV * HDIM];
static __device__ __half g_kbl[NTOK * NKV * HDIM];
static __device__ __half g_vbh[NTOK * NKV * HDIM];
static __device__ __half g_vbl[NTOK * NKV * HDIM];

static __device__ __half g_xh[NTOK * DMODEL];
static __device__ __half g_xl[NTOK * DMODEL];
static __device__ __half g_cth[NTOK * DMODEL];
static __device__ __half g_ctl[NTOK * DMODEL];
static __device__ __half g_wqh[DMODEL * (NH*HDIM)];
static __device__ __half g_wql[DMODEL * (NH*HDIM)];
static __device__ __half g_wkh[DMODEL * (NKV*HDIM)];
static __device__ __half g_wkl[DMODEL * (NKV*HDIM)];
static __device__ __half g_wvh[DMODEL * (NKV*HDIM)];
static __device__ __half g_wvl[DMODEL * (NKV*HDIM)];
static __device__ __half g_woh[DMODEL * DMODEL];
static __device__ __half g_wol[DMODEL * DMODEL];

// ---------------------------------------------------------------------------
// helpers
// ---------------------------------------------------------------------------
__device__ __forceinline__ uint32_t smem_u32(const void* p) {
  uint32_t a;
  asm("{ .reg .u64 t; cvta.to.shared.u64 t, %1; cvt.u32.u64 %0, t; }" : "=r"(a) : "l"(p));
  return a;
}

#define LDSM4(R, addr)                                                        \
  asm volatile("ldmatrix.sync.aligned.m8n8.x4.shared.b16 {%0,%1,%2,%3}, [%4];"\
    : "=r"((R)[0]), "=r"((R)[1]), "=r"((R)[2]), "=r"((R)[3]) : "r"(addr))

#define LDSM4T(R, addr)                                                       \
  asm volatile("ldmatrix.sync.aligned.m8n8.x4.trans.shared.b16 {%0,%1,%2,%3}, [%4];"\
    : "=r"((R)[0]), "=r"((R)[1]), "=r"((R)[2]), "=r"((R)[3]) : "r"(addr))

#define MMAF16(D, A, b0v, b1v)                                                \
  asm volatile("mma.sync.aligned.m16n8k16.row.col.f32.f16.f16.f32 "           \
    "{%0,%1,%2,%3}, {%4,%5,%6,%7}, {%8,%9}, {%0,%1,%2,%3};"                   \
    : "+f"((D)[0]), "+f"((D)[1]), "+f"((D)[2]), "+f"((D)[3])                  \
    : "r"((A)[0]), "r"((A)[1]), "r"((A)[2]), "r"((A)[3]), "r"(b0v), "r"(b1v))

#define CP_ASYNC16(dst, src) \
  asm volatile("cp.async.cg.shared.global [%0], [%1], 16;" :: "r"(dst), "l"(src))
#define CP_COMMIT() asm volatile("cp.async.commit_group;")

__device__ __forceinline__ void split16(float v, __half& h, __half& l) {
  h = __float2half_rn(v);
  l = __float2half_rn(v - __half2float(h));
}

// ---------------------------------------------------------------------------
// split fp32 -> fp16 hi/lo
// ---------------------------------------------------------------------------
__global__ void __launch_bounds__(256) split_kernel(const float* __restrict__ src,
    __half* __restrict__ hi, __half* __restrict__ lo, int n) {
  int i = blockIdx.x * 256 + threadIdx.x;
  if (i < n) {
    __half h, l;
    split16(src[i], h, l);
    hi[i] = h; lo[i] = l;
  }
}

// W [K,N] fp32 -> transposed fp16 hi/lo [N,K]
__global__ void __launch_bounds__(256) wsplit_kernel(const float* __restrict__ W,
    __half* __restrict__ th, __half* __restrict__ tl, int K, int N) {
  __shared__ float t[32][33];
  int n0 = blockIdx.x * 32, k0 = blockIdx.y * 32;
  int x = threadIdx.x, y = threadIdx.y;  // 32 x 8
  #pragma unroll
  for (int i = 0; i < 4; i++)
    t[y * 4 + i][x] = W[(size_t)(k0 + y * 4 + i) * N + n0 + x];
  __syncthreads();
  #pragma unroll
  for (int i = 0; i < 4; i++) {
    int n = n0 + y * 4 + i;
    __half h, l;
    split16(t[x][y * 4 + i], h, l);
    th[(size_t)n * K + k0 + x] = h;
    tl[(size_t)n * K + k0 + x] = l;
  }
}

// ---------------------------------------------------------------------------
// mma.sync GEMM, fp16 split: C = A @ B^T (B stored [N,K]).
// BTERMS=3: AhBh + AhBl + AlBh (near-exact). BTERMS=2: AhBh + AlBh (B hi only).
// 2-stage, 80KB smem, 2 CTAs/SM.
// ---------------------------------------------------------------------------
#define GBM 128
#define GBN 128
#define GBK 32
#define RSTRIDE 80
#define TILE_BYTES (128 * RSTRIDE)
#define STG_BYTES (4 * TILE_BYTES)
#define GEMM_SMEM (2 * STG_BYTES)

template <int BTERMS>
__global__ void __launch_bounds__(256, 2) gemm_kernel(
    const __half* __restrict__ Ah, const __half* __restrict__ Al,
    const __half* __restrict__ Bh, const __half* __restrict__ Bl,
    float* __restrict__ Cf, __half* __restrict__ Ch,
    __half* __restrict__ Cl, int K, int N) {
  extern __shared__ char smem[];
  uint32_t sbase = smem_u32(smem);
  int tid = threadIdx.x;
  int wid = tid >> 5, lane = tid & 31;
  int wm = wid >> 1, wn = wid & 1;
  int bm = blockIdx.y * GBM, bn = blockIdx.x * GBN;
  int nc = K / GBK;

  const __half* srcs[4] = {Ah, Al, Bh, Bl};
  int rbase[4] = {bm, bm, bn, bn};

  auto load_chunk = [&](int c, int buf) {
    int k0 = c * GBK;
    #pragma unroll
    for (int i = 0; i < 8; i++) {
      if (BTERMS == 2 && i >= 6) continue;   // skip Bl tile
      int idx = tid + i * 256;
      int t = i >> 1;
      int r = (idx >> 2) & 127;
      int g = idx & 3;
      uint32_t dst = sbase + buf * STG_BYTES + t * TILE_BYTES + r * RSTRIDE + g * 16;
      const __half* src = srcs[t] + (size_t)(rbase[t] + r) * K + k0 + g * 8;
      CP_ASYNC16(dst, src);
    }
    CP_COMMIT();
  };

  float acc[2][8][4];
  #pragma unroll
  for (int mi = 0; mi < 2; mi++)
    #pragma unroll
    for (int ni = 0; ni < 8; ni++)
      #pragma unroll
      for (int j = 0; j < 4; j++) acc[mi][ni][j] = 0.f;

  load_chunk(0, 0);
  int lrow = lane & 15, lk8 = (lane >> 4) * 8;

  for (int c = 0; c < nc; c++) {
    if (c + 1 < nc) {
      load_chunk(c + 1, (c + 1) & 1);
      asm volatile("cp.async.wait_group 1;");
    } else {
      asm volatile("cp.async.wait_group 0;");
    }
    __syncthreads();

    uint32_t b0 = sbase + (c & 1) * STG_BYTES;
    uint32_t aHs = b0, aLs = b0 + TILE_BYTES;
    uint32_t bHs = b0 + 2 * TILE_BYTES, bLs = b0 + 3 * TILE_BYTES;

    #pragma unroll
    for (int kk = 0; kk < GBK; kk += 16) {
      uint32_t ah[2][4], al[2][4];
      uint32_t aoff = (uint32_t)(wm * 32 + lrow) * RSTRIDE + (kk + lk8) * 2;
      LDSM4(ah[0], aHs + aoff);
      LDSM4(ah[1], aHs + aoff + 16 * RSTRIDE);
      LDSM4(al[0], aLs + aoff);
      LDSM4(al[1], aLs + aoff + 16 * RSTRIDE);
      #pragma unroll
      for (int p = 0; p < 4; p++) {
        uint32_t boff = (uint32_t)(wn * 64 + p * 16 + lrow) * RSTRIDE + (kk + lk8) * 2;
        uint32_t h[4];
        LDSM4(h, bHs + boff);
        #pragma unroll
        for (int mi = 0; mi < 2; mi++) {
          MMAF16(acc[mi][2 * p],     ah[mi], h[0], h[2]);
          MMAF16(acc[mi][2 * p + 1], ah[mi], h[1], h[3]);
          MMAF16(acc[mi][2 * p],     al[mi], h[0], h[2]);
          MMAF16(acc[mi][2 * p + 1], al[mi], h[1], h[3]);
        }
        if (BTERMS == 3) {
          uint32_t l[4];
          LDSM4(l, bLs + boff);
          #pragma unroll
          for (int mi = 0; mi < 2; mi++) {
            MMAF16(acc[mi][2 * p],     ah[mi], l[0], l[2]);
            MMAF16(acc[mi][2 * p + 1], ah[mi], l[1], l[3]);
          }
        }
      }
    }
    __syncthreads();
  }

  int gid = lane >> 2, cid = lane & 3;
  if (Cf) {
    #pragma unroll
    for (int mi = 0; mi < 2; mi++)
      #pragma unroll
      for (int ni = 0; ni < 8; ni++) {
        int row = bm + wm * 32 + mi * 16 + gid;
        int col = bn + wn * 64 + ni * 8 + cid * 2;
        *(float2*)(Cf + (size_t)row * N + col) =
            make_float2(acc[mi][ni][0], acc[mi][ni][1]);
        *(float2*)(Cf + (size_t)(row + 8) * N + col) =
            make_float2(acc[mi][ni][2], acc[mi][ni][3]);
      }
  } else {
    #pragma unroll
    for (int mi = 0; mi < 2; mi++)
      #pragma unroll
      for (int ni = 0; ni < 8; ni++) {
        int row = bm + wm * 32 + mi * 16 + gid;
        int col = bn + wn * 64 + ni * 8 + cid * 2;
        #pragma unroll
        for (int half = 0; half < 2; half++) {
          __half h0, l0, h1, l1;
          split16(acc[mi][ni][2 * half], h0, l0);
          split16(acc[mi][ni][2 * half + 1], h1, l1);
          __half2 hh; hh.x = h0; hh.y = h1;
          __half2 ll; ll.x = l0; ll.y = l1;
          size_t o = (size_t)(row + half * 8) * N + col;
          *(__half2*)(Ch + o) = hh;
          *(__half2*)(Cl + o) = ll;
        }
      }
  }
}

// ---------------------------------------------------------------------------
// RoPE + L2 norm: reads fp32 q/k, writes split fp16 only.
// ---------------------------------------------------------------------------
__global__ void __launch_bounds__(64) rope_norm_kernel() {
  int tok = blockIdx.x;
  int r = blockIdx.y;
  size_t off = (r < NH) ? ((size_t)tok * NH + r) * HDIM
                        : ((size_t)tok * NKV + (r - NH)) * HDIM;
  const float* base = (r < NH) ? g_q + off : g_k + off;
  __half* bh = (r < NH) ? g_qh + off : g_kbh + off;
  __half* bl = (r < NH) ? g_ql + off : g_kbl + off;
  int pos = tok & (SEQ - 1);
  int i = threadIdx.x;  // pair 0..63
  float t0 = base[2 * i], t1 = base[2 * i + 1];
  float inv = exp2f((float)(2 * i) * (-13.287712379549449f / 128.0f));
  float ang = (float)pos * inv;
  float sn, cs;
  sincosf(ang, &sn, &cs);
  float r0 = t0 * cs - t1 * sn;
  float r1 = t0 * sn + t1 * cs;
  float ss = r0 * r0 + r1 * r1;
  #pragma unroll
  for (int o = 16; o; o >>= 1) ss += __shfl_xor_sync(0xffffffffu, ss, o);
  __shared__ float part[2];
  if ((i & 31) == 0) part[i >> 5] = ss;
  __syncthreads();
  float sc = rsqrtf((part[0] + part[1]) * (1.0f / 128.0f) + 1e-6f);
  __half h0, l0, h1, l1;
  split16(r0 * sc, h0, l0);
  split16(r1 * sc, h1, l1);
  bh[2 * i] = h0; bh[2 * i + 1] = h1;
  bl[2 * i] = l0; bl[2 * i + 1] = l1;
}

// ---------------------------------------------------------------------------
// MMA attention: QK fp16x3 (near-exact scores), AV 2-term (V fully corrected,
// P single fp16 plane). Epilogue writes split fp16 ctx directly.
// ---------------------------------------------------------------------------
#define SCW 2056
#define PAD_STR 272
#define OFF_QH 131584
#define OFF_QL (OFF_QH + 16*PAD_STR)
#define OFF_KH (OFF_QL + 16*PAD_STR)
#define OFF_KL (OFF_KH + 128*PAD_STR)
#define OFF_PH (OFF_KL + 128*PAD_STR)
#define OFF_RED (OFF_PH + 16*PAD_STR)
#define ATTN_SMEM (OFF_RED + 128)

__global__ void __launch_bounds__(256, 1) attn_mma_kernel(
    float* __restrict__ attn_out, int write_attn) {
  extern __shared__ char smc[];
  float* s_scores = (float*)smc;
  float* s_red = (float*)(smc + OFF_RED);
  uint32_t sb = smem_u32(smc);

  int qb = gridDim.x - 1 - blockIdx.x;
  int h = blockIdx.y, b = blockIdx.z;
  int hk = h >> 2;
  int tid = threadIdx.x, w = tid >> 5, lane = tid & 31;
  int kend = qb * 16 + 16;
  const float SC = 0.08838834764831845f;
  int lrow = lane & 15, lhi = lane >> 4;

  {
    int r = tid >> 4, g = tid & 15;
    size_t go = ((size_t)(b * SEQ + qb * 16 + r) * NH + h) * HDIM + g * 8;
    *(uint4*)(smc + OFF_QH + r * PAD_STR + g * 16) = *(const uint4*)(g_qh + go);
    *(uint4*)(smc + OFF_QL + r * PAD_STR + g * 16) = *(const uint4*)(g_ql + go);
  }
  __syncthreads();

  uint32_t aH[8][4], aL[8][4];
  #pragma unroll
  for (int kk = 0; kk < 8; kk++) {
    uint32_t off = lrow * PAD_STR + kk * 32 + lhi * 16;
    LDSM4(aH[kk], sb + OFF_QH + off);
    LDSM4(aL[kk], sb + OFF_QL + off);
  }

  // ---- scores (fp16x3) ----
  for (int kc = 0; kc < kend; kc += 128) {
    __syncthreads();
    for (int idx = tid; idx < 128 * 16; idx += 256) {
      int j = idx >> 4, g = idx & 15;
      uint4 vh = {0, 0, 0, 0}, vl = {0, 0, 0, 0};
      if (kc + j < kend) {
        size_t go = ((size_t)(b * SEQ + kc + j) * NKV + hk) * HDIM + g * 8;
        vh = *(const uint4*)(g_kbh + go);
        vl = *(const uint4*)(g_kbl + go);
      }
      *(uint4*)(smc + OFF_KH + j * PAD_STR + g * 16) = vh;
      *(uint4*)(smc + OFF_KL + j * PAD_STR + g * 16) = vl;
    }
    __syncthreads();

    float acc[2][4] = {{0, 0, 0, 0}, {0, 0, 0, 0}};
    int n0 = w * 16;
    #pragma unroll
    for (int kk = 0; kk < 8; kk++) {
      uint32_t off = (n0 + lrow) * PAD_STR + kk * 32 + lhi * 16;
      uint32_t bh[4], bl[4];
      LDSM4(bh, sb + OFF_KH + off);
      LDSM4(bl, sb + OFF_KL + off);
      MMAF16(acc[0], aH[kk], bh[0], bh[2]);
      MMAF16(acc[1], aH[kk], bh[1], bh[3]);
      MMAF16(acc[0], aH[kk], bl[0], bl[2]);
      MMAF16(acc[1], aH[kk], bl[1], bl[3]);
      MMAF16(acc[0], aL[kk], bh[0], bh[2]);
      MMAF16(acc[1], aL[kk], bh[1], bh[3]);
    }
    int r0 = lane >> 2, c0 = (lane & 3) * 2;
    int qs0 = qb * 16;
    #pragma unroll
    for (int nt = 0; nt < 2; nt++) {
      int col = kc + n0 + nt * 8 + c0;
      s_scores[r0 * SCW + col]           = (col     <= qs0 + r0)     ? acc[nt][0] * SC : -1e30f;
      s_scores[r0 * SCW + col + 1]       = (col + 1 <= qs0 + r0)     ? acc[nt][1] * SC : -1e30f;
      s_scores[(r0 + 8) * SCW + col]     = (col     <= qs0 + r0 + 8) ? acc[nt][2] * SC : -1e30f;
      s_scores[(r0 + 8) * SCW + col + 1] = (col + 1 <= qs0 + r0 + 8) ? acc[nt][3] * SC : -1e30f;
    }
  }
  __syncthreads();

  // ---- softmax stats ----
  {
    int qi = tid >> 4, r = tid & 15;
    float m = -1e30f;
    for (int j = r; j < kend; j += 16) m = fmaxf(m, s_scores[qi * SCW + j]);
    #pragma unroll
    for (int o = 8; o; o >>= 1) m = fmaxf(m, __shfl_xor_sync(0xffffffffu, m, o));
    float s = 0.f;
    for (int j = r; j < kend; j += 16) s += __expf(s_scores[qi * SCW + j] - m);
    #pragma unroll
    for (int o = 8; o; o >>= 1) s += __shfl_xor_sync(0xffffffffu, s, o);
    if (r == 0) { s_red[qi] = m; s_red[16 + qi] = 1.0f / s; }
  }
  __syncthreads();

  // ---- attn prob output ----
  if (write_attn) {
    float* ab = attn_out + ((size_t)(b * NH + h) * SEQ + (size_t)qb * 16) * SEQ;
    for (int idx = tid; idx < 16 * 512; idx += 256) {
      int qi = idx >> 9, j4 = (idx & 511) * 4;
      float m = s_red[qi], inv = s_red[16 + qi];
      float4 p = {0, 0, 0, 0};
      if (j4 < kend) {
        p.x = __expf(s_scores[qi * SCW + j4] - m) * inv;
        if (j4 + 1 < kend) p.y = __expf(s_scores[qi * SCW + j4 + 1] - m) * inv;
        if (j4 + 2 < kend) p.z = __expf(s_scores[qi * SCW + j4 + 2] - m) * inv;
        if (j4 + 3 < kend) p.w = __expf(s_scores[qi * SCW + j4 + 3] - m) * inv;
      }
      *(float4*)(ab + (size_t)qi * SEQ + j4) = p;
    }
  }

  // ---- AV (2-term: Ph·Vh + Ph·Vl) ----
  float oacc[2][4] = {{0, 0, 0, 0}, {0, 0, 0, 0}};
  for (int kc = 0; kc < kend; kc += 128) {
    __syncthreads();
    for (int idx = tid; idx < 128 * 16; idx += 256) {
      int j = idx >> 4, g = idx & 15;
      uint4 vh = {0, 0, 0, 0}, vl = {0, 0, 0, 0};
      if (kc + j < kend) {
        size_t go = ((size_t)(b * SEQ + kc + j) * NKV + hk) * HDIM + g * 8;
        vh = *(const uint4*)(g_vbh + go);
        vl = *(const uint4*)(g_vbl + go);
      }
      *(uint4*)(smc + OFF_KH + j * PAD_STR + g * 16) = vh;
      *(uint4*)(smc + OFF_KL + j * PAD_STR + g * 16) = vl;
    }
    for (int idx = tid; idx < 16 * 64; idx += 256) {
      int r = idx >> 6, c2 = (idx & 63) * 2;
      float m = s_red[r], inv = s_red[16 + r];
      float p0 = 0.f, p1 = 0.f;
      if (kc + c2 < kend)     p0 = __expf(s_scores[r * SCW + kc + c2] - m) * inv;
      if (kc + c2 + 1 < kend) p1 = __expf(s_scores[r * SCW + kc + c2 + 1] - m) * inv;
      __half2 hh;
      hh.x = __float2half_rn(p0);
      hh.y = __float2half_rn(p1);
      *(__half2*)(smc + OFF_PH + r * PAD_STR + c2 * 2) = hh;
    }
    __syncthreads();

    #pragma unroll
    for (int kk = 0; kk < 8; kk++) {
      uint32_t pOff = lrow * PAD_STR + kk * 32 + lhi * 16;
      uint32_t ph[4];
      LDSM4(ph, sb + OFF_PH + pOff);
      uint32_t vOff = (kk * 16 + lrow) * PAD_STR + w * 32 + lhi * 16;
      uint32_t vh[4], vl[4];
      LDSM4T(vh, sb + OFF_KH + vOff);
      LDSM4T(vl, sb + OFF_KL + vOff);
      MMAF16(oacc[0], ph, vh[0], vh[1]);
      MMAF16(oacc[1], ph, vh[2], vh[3]);
      MMAF16(oacc[0], ph, vl[0], vl[1]);
      MMAF16(oacc[1], ph, vl[2], vl[3]);
    }
  }

  // epilogue: split ctx fp16 [tok, H*HD]
  {
    int r0 = lane >> 2, c0 = (lane & 3) * 2;
    #pragma unroll
    for (int nt = 0; nt < 2; nt++) {
      int col = w * 16 + nt * 8 + c0;
      #pragma unroll
      for (int half = 0; half < 2; half++) {
        __half h0, l0, h1, l1;
        split16(oacc[nt][2 * half], h0, l0);
        split16(oacc[nt][2 * half + 1], h1, l1);
        __half2 hh; hh.x = h0; hh.y = h1;
        __half2 ll; ll.x = l0; ll.y = l1;
        size_t o = ((size_t)(b * SEQ + qb * 16 + r0 + half * 8)) * DMODEL
                 + h * HDIM + col;
        *(__half2*)(g_cth + o) = hh;
        *(__half2*)(g_ctl + o) = ll;
      }
    }
  }
}

// ---------------------------------------------------------------------------
extern "C" void kernel_launch(void* const* d_in, const int* in_sizes, int n_in,
                              void* d_out, int out_size) {
  const float* x  = (const float*)d_in[0];
  const float* Wq = (const float*)d_in[1];
  const float* Wk = (const float*)d_in[2];
  const float* Wv = (const float*)d_in[3];
  const float* Wo = (const float*)d_in[4];
  float* out = (float*)d_out;
  float* attn = out + (size_t)NTOK * DMODEL;
  long long need = (long long)NTOK * DMODEL + (long long)BATCH * NH * SEQ * SEQ;
  int write_attn = ((long long)out_size >= need) ? 1 : 0;

  float *gq, *gk;
  __half *xh, *xl, *cth, *ctl, *vbh, *vbl;
  __half *wqh, *wql, *wkh, *wkl, *wvh, *wvl, *woh, *wol;
  cudaGetSymbolAddress((void**)&gq, g_q);
  cudaGetSymbolAddress((void**)&gk, g_k);
  cudaGetSymbolAddress((void**)&xh, g_xh);
  cudaGetSymbolAddress((void**)&xl, g_xl);
  cudaGetSymbolAddress((void**)&cth, g_cth);
  cudaGetSymbolAddress((void**)&ctl, g_ctl);
  cudaGetSymbolAddress((void**)&vbh, g_vbh);
  cudaGetSymbolAddress((void**)&vbl, g_vbl);
  cudaGetSymbolAddress((void**)&wqh, g_wqh);
  cudaGetSymbolAddress((void**)&wql, g_wql);
  cudaGetSymbolAddress((void**)&wkh, g_wkh);
  cudaGetSymbolAddress((void**)&wkl, g_wkl);
  cudaGetSymbolAddress((void**)&wvh, g_wvh);
  cudaGetSymbolAddress((void**)&wvl, g_wvl);
  cudaGetSymbolAddress((void**)&woh, g_woh);
  cudaGetSymbolAddress((void**)&wol, g_wol);

  cudaFuncSetAttribute(gemm_kernel<3>, cudaFuncAttributeMaxDynamicSharedMemorySize,
                       GEMM_SMEM);
  cudaFuncSetAttribute(gemm_kernel<2>, cudaFuncAttributeMaxDynamicSharedMemorySize,
                       GEMM_SMEM);
  cudaFuncSetAttribute(attn_mma_kernel, cudaFuncAttributeMaxDynamicSharedMemorySize,
                       ATTN_SMEM);

  {
    int n = NTOK * DMODEL;
    split_kernel<<<(n + 255) / 256, 256>>>(x, xh, xl, n);
  }
  wsplit_kernel<<<dim3((NH*HDIM)/32, DMODEL/32), dim3(32, 8)>>>(Wq, wqh, wql, DMODEL, NH*HDIM);
  wsplit_kernel<<<dim3((NKV*HDIM)/32, DMODEL/32), dim3(32, 8)>>>(Wk, wkh, wkl, DMODEL, NKV*HDIM);
  wsplit_kernel<<<dim3((NKV*HDIM)/32, DMODEL/32), dim3(32, 8)>>>(Wv, wvh, wvl, DMODEL, NKV*HDIM);
  wsplit_kernel<<<dim3(DMODEL/32, DMODEL/32), dim3(32, 8)>>>(Wo, woh, wol, DMODEL, DMODEL);

  // Q/K projections: 3-term (score path must stay near-exact)
  gemm_kernel<3><<<dim3((NH*HDIM)/GBN, NTOK/GBM), 256, GEMM_SMEM>>>(
      xh, xl, wqh, wql, gq, nullptr, nullptr, DMODEL, NH*HDIM);
  gemm_kernel<3><<<dim3((NKV*HDIM)/GBN, NTOK/GBM), 256, GEMM_SMEM>>>(
      xh, xl, wkh, wkl, gk, nullptr, nullptr, DMODEL, NKV*HDIM);
  // V projection: 2-term (Wv hi only), writes split fp16 V directly
  gemm_kernel<2><<<dim3((NKV*HDIM)/GBN, NTOK/GBM), 256, GEMM_SMEM>>>(
      xh, xl, wvh, wvl, nullptr, vbh, vbl, DMODEL, NKV*HDIM);

  rope_norm_kernel<<<dim3(NTOK, NH + NKV), 64>>>();

  attn_mma_kernel<<<dim3(SEQ / 16, NH, BATCH), 256, ATTN_SMEM>>>(attn, write_attn);

  // output projection: 2-term (Wo hi only)
  gemm_kernel<2><<<dim3(DMODEL/GBN, NTOK/GBM), 256, GEMM_SMEM>>>(
      cth, ctl, woh, wol, out, nullptr, nullptr, DMODEL, DMODEL);
}

// round 13
// speedup vs baseline: 2.6258x; 1.1506x over previous
#include <cuda_runtime.h>
#include <cuda_fp16.h>
#include <math.h>
#include <stdint.h>

#define NH     16
#define NKV    4
#define HDIM   128
#define BATCH  2
#define SEQ    2048
#define DMODEL 2048
#define NTOK   (BATCH*SEQ)

// ---------------------------------------------------------------------------
// scratch
// ---------------------------------------------------------------------------
static __device__ float g_q[NTOK * NH * HDIM];
static __device__ float g_k[NTOK * NKV * HDIM];

static __device__ __half g_qh[NTOK * NH * HDIM];
static __device__ __half g_ql[NTOK * NH * HDIM];
static __device__ __half g_kbh[NTOK * NKV * HDIM];
static __device__ __half g_vbh[NTOK * NKV * HDIM];
static __device__ __half g_vbl[NTOK * NKV * HDIM];

static __device__ __half g_xh[NTOK * DMODEL];
static __device__ __half g_xl[NTOK * DMODEL];
static __device__ __half g_cth[NTOK * DMODEL];
static __device__ __half g_ctl[NTOK * DMODEL];
static __device__ __half g_wqh[DMODEL * (NH*HDIM)];
static __device__ __half g_wql[DMODEL * (NH*HDIM)];
static __device__ __half g_wkh[DMODEL * (NKV*HDIM)];
static __device__ __half g_wkl[DMODEL * (NKV*HDIM)];
static __device__ __half g_wvh[DMODEL * (NKV*HDIM)];
static __device__ __half g_wvl[DMODEL * (NKV*HDIM)];
static __device__ __half g_woh[DMODEL * DMODEL];
static __device__ __half g_wol[DMODEL * DMODEL];

// ---------------------------------------------------------------------------
// helpers
// ---------------------------------------------------------------------------
__device__ __forceinline__ uint32_t smem_u32(const void* p) {
  uint32_t a;
  asm("{ .reg .u64 t; cvta.to.shared.u64 t, %1; cvt.u32.u64 %0, t; }" : "=r"(a) : "l"(p));
  return a;
}

#define LDSM4(R, addr)                                                        \
  asm volatile("ldmatrix.sync.aligned.m8n8.x4.shared.b16 {%0,%1,%2,%3}, [%4];"\
    : "=r"((R)[0]), "=r"((R)[1]), "=r"((R)[2]), "=r"((R)[3]) : "r"(addr))

#define LDSM4T(R, addr)                                                       \
  asm volatile("ldmatrix.sync.aligned.m8n8.x4.trans.shared.b16 {%0,%1,%2,%3}, [%4];"\
    : "=r"((R)[0]), "=r"((R)[1]), "=r"((R)[2]), "=r"((R)[3]) : "r"(addr))

#define MMAF16(D, A, b0v, b1v)                                                \
  asm volatile("mma.sync.aligned.m16n8k16.row.col.f32.f16.f16.f32 "           \
    "{%0,%1,%2,%3}, {%4,%5,%6,%7}, {%8,%9}, {%0,%1,%2,%3};"                   \
    : "+f"((D)[0]), "+f"((D)[1]), "+f"((D)[2]), "+f"((D)[3])                  \
    : "r"((A)[0]), "r"((A)[1]), "r"((A)[2]), "r"((A)[3]), "r"(b0v), "r"(b1v))

#define CP_ASYNC16(dst, src) \
  asm volatile("cp.async.cg.shared.global [%0], [%1], 16;" :: "r"(dst), "l"(src))
#define CP_COMMIT() asm volatile("cp.async.commit_group;")

__device__ __forceinline__ void split16(float v, __half& h, __half& l) {
  h = __float2half_rn(v);
  l = __float2half_rn(v - __half2float(h));
}

// ---------------------------------------------------------------------------
// split fp32 -> fp16 hi/lo
// ---------------------------------------------------------------------------
__global__ void __launch_bounds__(256) split_kernel(const float* __restrict__ src,
    __half* __restrict__ hi, __half* __restrict__ lo, int n) {
  int i = blockIdx.x * 256 + threadIdx.x;
  if (i < n) {
    __half h, l;
    split16(src[i], h, l);
    hi[i] = h; lo[i] = l;
  }
}

// W [K,N] fp32 -> transposed fp16 hi/lo [N,K]
__global__ void __launch_bounds__(256) wsplit_kernel(const float* __restrict__ W,
    __half* __restrict__ th, __half* __restrict__ tl, int K, int N) {
  __shared__ float t[32][33];
  int n0 = blockIdx.x * 32, k0 = blockIdx.y * 32;
  int x = threadIdx.x, y = threadIdx.y;  // 32 x 8
  #pragma unroll
  for (int i = 0; i < 4; i++)
    t[y * 4 + i][x] = W[(size_t)(k0 + y * 4 + i) * N + n0 + x];
  __syncthreads();
  #pragma unroll
  for (int i = 0; i < 4; i++) {
    int n = n0 + y * 4 + i;
    __half h, l;
    split16(t[x][y * 4 + i], h, l);
    th[(size_t)n * K + k0 + x] = h;
    tl[(size_t)n * K + k0 + x] = l;
  }
}

// ---------------------------------------------------------------------------
// mma.sync GEMM, fp16 split: C = A @ B^T (B stored [N,K]).
// BTERMS=3: AhBh + AhBl + AlBh. BTERMS=2: AhBh + AlBh (B hi only).
// 2-stage, 80KB smem, 2 CTAs/SM.
// ---------------------------------------------------------------------------
#define GBM 128
#define GBN 128
#define GBK 32
#define RSTRIDE 80
#define TILE_BYTES (128 * RSTRIDE)
#define STG_BYTES (4 * TILE_BYTES)
#define GEMM_SMEM (2 * STG_BYTES)

template <int BTERMS>
__global__ void __launch_bounds__(256, 2) gemm_kernel(
    const __half* __restrict__ Ah, const __half* __restrict__ Al,
    const __half* __restrict__ Bh, const __half* __restrict__ Bl,
    float* __restrict__ Cf, __half* __restrict__ Ch,
    __half* __restrict__ Cl, int K, int N) {
  extern __shared__ char smem[];
  uint32_t sbase = smem_u32(smem);
  int tid = threadIdx.x;
  int wid = tid >> 5, lane = tid & 31;
  int wm = wid >> 1, wn = wid & 1;
  int bm = blockIdx.y * GBM, bn = blockIdx.x * GBN;
  int nc = K / GBK;

  const __half* srcs[4] = {Ah, Al, Bh, Bl};
  int rbase[4] = {bm, bm, bn, bn};

  auto load_chunk = [&](int c, int buf) {
    int k0 = c * GBK;
    #pragma unroll
    for (int i = 0; i < 8; i++) {
      if (BTERMS == 2 && i >= 6) continue;   // skip Bl tile
      int idx = tid + i * 256;
      int t = i >> 1;
      int r = (idx >> 2) & 127;
      int g = idx & 3;
      uint32_t dst = sbase + buf * STG_BYTES + t * TILE_BYTES + r * RSTRIDE + g * 16;
      const __half* src = srcs[t] + (size_t)(rbase[t] + r) * K + k0 + g * 8;
      CP_ASYNC16(dst, src);
    }
    CP_COMMIT();
  };

  float acc[2][8][4];
  #pragma unroll
  for (int mi = 0; mi < 2; mi++)
    #pragma unroll
    for (int ni = 0; ni < 8; ni++)
      #pragma unroll
      for (int j = 0; j < 4; j++) acc[mi][ni][j] = 0.f;

  load_chunk(0, 0);
  int lrow = lane & 15, lk8 = (lane >> 4) * 8;

  for (int c = 0; c < nc; c++) {
    if (c + 1 < nc) {
      load_chunk(c + 1, (c + 1) & 1);
      asm volatile("cp.async.wait_group 1;");
    } else {
      asm volatile("cp.async.wait_group 0;");
    }
    __syncthreads();

    uint32_t b0 = sbase + (c & 1) * STG_BYTES;
    uint32_t aHs = b0, aLs = b0 + TILE_BYTES;
    uint32_t bHs = b0 + 2 * TILE_BYTES, bLs = b0 + 3 * TILE_BYTES;

    #pragma unroll
    for (int kk = 0; kk < GBK; kk += 16) {
      uint32_t ah[2][4], al[2][4];
      uint32_t aoff = (uint32_t)(wm * 32 + lrow) * RSTRIDE + (kk + lk8) * 2;
      LDSM4(ah[0], aHs + aoff);
      LDSM4(ah[1], aHs + aoff + 16 * RSTRIDE);
      LDSM4(al[0], aLs + aoff);
      LDSM4(al[1], aLs + aoff + 16 * RSTRIDE);
      #pragma unroll
      for (int p = 0; p < 4; p++) {
        uint32_t boff = (uint32_t)(wn * 64 + p * 16 + lrow) * RSTRIDE + (kk + lk8) * 2;
        uint32_t h[4];
        LDSM4(h, bHs + boff);
        #pragma unroll
        for (int mi = 0; mi < 2; mi++) {
          MMAF16(acc[mi][2 * p],     ah[mi], h[0], h[2]);
          MMAF16(acc[mi][2 * p + 1], ah[mi], h[1], h[3]);
          MMAF16(acc[mi][2 * p],     al[mi], h[0], h[2]);
          MMAF16(acc[mi][2 * p + 1], al[mi], h[1], h[3]);
        }
        if (BTERMS == 3) {
          uint32_t l[4];
          LDSM4(l, bLs + boff);
          #pragma unroll
          for (int mi = 0; mi < 2; mi++) {
            MMAF16(acc[mi][2 * p],     ah[mi], l[0], l[2]);
            MMAF16(acc[mi][2 * p + 1], ah[mi], l[1], l[3]);
          }
        }
      }
    }
    __syncthreads();
  }

  int gid = lane >> 2, cid = lane & 3;
  if (Cf) {
    #pragma unroll
    for (int mi = 0; mi < 2; mi++)
      #pragma unroll
      for (int ni = 0; ni < 8; ni++) {
        int row = bm + wm * 32 + mi * 16 + gid;
        int col = bn + wn * 64 + ni * 8 + cid * 2;
        *(float2*)(Cf + (size_t)row * N + col) =
            make_float2(acc[mi][ni][0], acc[mi][ni][1]);
        *(float2*)(Cf + (size_t)(row + 8) * N + col) =
            make_float2(acc[mi][ni][2], acc[mi][ni][3]);
      }
  } else {
    #pragma unroll
    for (int mi = 0; mi < 2; mi++)
      #pragma unroll
      for (int ni = 0; ni < 8; ni++) {
        int row = bm + wm * 32 + mi * 16 + gid;
        int col = bn + wn * 64 + ni * 8 + cid * 2;
        #pragma unroll
        for (int half = 0; half < 2; half++) {
          __half h0, l0, h1, l1;
          split16(acc[mi][ni][2 * half], h0, l0);
          split16(acc[mi][ni][2 * half + 1], h1, l1);
          __half2 hh; hh.x = h0; hh.y = h1;
          __half2 ll; ll.x = l0; ll.y = l1;
          size_t o = (size_t)(row + half * 8) * N + col;
          *(__half2*)(Ch + o) = hh;
          *(__half2*)(Cl + o) = ll;
        }
      }
  }
}

// ---------------------------------------------------------------------------
// RoPE + L2 norm: q -> split fp16 (hi+lo); k -> hi only (QK is 2-term).
// ---------------------------------------------------------------------------
__global__ void __launch_bounds__(64) rope_norm_kernel() {
  int tok = blockIdx.x;
  int r = blockIdx.y;
  size_t off = (r < NH) ? ((size_t)tok * NH + r) * HDIM
                        : ((size_t)tok * NKV + (r - NH)) * HDIM;
  const float* base = (r < NH) ? g_q + off : g_k + off;
  int pos = tok & (SEQ - 1);
  int i = threadIdx.x;  // pair 0..63
  float t0 = base[2 * i], t1 = base[2 * i + 1];
  float inv = exp2f((float)(2 * i) * (-13.287712379549449f / 128.0f));
  float ang = (float)pos * inv;
  float sn, cs;
  sincosf(ang, &sn, &cs);
  float r0 = t0 * cs - t1 * sn;
  float r1 = t0 * sn + t1 * cs;
  float ss = r0 * r0 + r1 * r1;
  #pragma unroll
  for (int o = 16; o; o >>= 1) ss += __shfl_xor_sync(0xffffffffu, ss, o);
  __shared__ float part[2];
  if ((i & 31) == 0) part[i >> 5] = ss;
  __syncthreads();
  float sc = rsqrtf((part[0] + part[1]) * (1.0f / 128.0f) + 1e-6f);
  float v0 = r0 * sc, v1 = r1 * sc;
  if (r < NH) {
    __half h0, l0, h1, l1;
    split16(v0, h0, l0);
    split16(v1, h1, l1);
    g_qh[off + 2 * i] = h0; g_qh[off + 2 * i + 1] = h1;
    g_ql[off + 2 * i] = l0; g_ql[off + 2 * i + 1] = l1;
  } else {
    g_kbh[off + 2 * i] = __float2half_rn(v0);
    g_kbh[off + 2 * i + 1] = __float2half_rn(v1);
  }
}

// ---------------------------------------------------------------------------
// MMA attention: QK 2-term (Qh·Kh + Ql·Kh), AV 2-term (Ph·Vh + Ph·Vl).
// ---------------------------------------------------------------------------
#define SCW 2056
#define PAD_STR 272
#define OFF_QH 131584
#define OFF_QL (OFF_QH + 16*PAD_STR)
#define OFF_KH (OFF_QL + 16*PAD_STR)
#define OFF_KL (OFF_KH + 128*PAD_STR)
#define OFF_PH (OFF_KL + 128*PAD_STR)
#define OFF_RED (OFF_PH + 16*PAD_STR)
#define ATTN_SMEM (OFF_RED + 128)

__global__ void __launch_bounds__(256, 1) attn_mma_kernel(
    float* __restrict__ attn_out, int write_attn) {
  extern __shared__ char smc[];
  float* s_scores = (float*)smc;
  float* s_red = (float*)(smc + OFF_RED);
  uint32_t sb = smem_u32(smc);

  int qb = gridDim.x - 1 - blockIdx.x;
  int h = blockIdx.y, b = blockIdx.z;
  int hk = h >> 2;
  int tid = threadIdx.x, w = tid >> 5, lane = tid & 31;
  int kend = qb * 16 + 16;
  const float SC = 0.08838834764831845f;
  int lrow = lane & 15, lhi = lane >> 4;

  {
    int r = tid >> 4, g = tid & 15;
    size_t go = ((size_t)(b * SEQ + qb * 16 + r) * NH + h) * HDIM + g * 8;
    *(uint4*)(smc + OFF_QH + r * PAD_STR + g * 16) = *(const uint4*)(g_qh + go);
    *(uint4*)(smc + OFF_QL + r * PAD_STR + g * 16) = *(const uint4*)(g_ql + go);
  }
  __syncthreads();

  uint32_t aH[8][4], aL[8][4];
  #pragma unroll
  for (int kk = 0; kk < 8; kk++) {
    uint32_t off = lrow * PAD_STR + kk * 32 + lhi * 16;
    LDSM4(aH[kk], sb + OFF_QH + off);
    LDSM4(aL[kk], sb + OFF_QL + off);
  }

  // ---- scores (2-term; only K-hi in smem) ----
  for (int kc = 0; kc < kend; kc += 128) {
    __syncthreads();
    for (int idx = tid; idx < 128 * 16; idx += 256) {
      int j = idx >> 4, g = idx & 15;
      uint4 vh = {0, 0, 0, 0};
      if (kc + j < kend) {
        size_t go = ((size_t)(b * SEQ + kc + j) * NKV + hk) * HDIM + g * 8;
        vh = *(const uint4*)(g_kbh + go);
      }
      *(uint4*)(smc + OFF_KH + j * PAD_STR + g * 16) = vh;
    }
    __syncthreads();

    float acc[2][4] = {{0, 0, 0, 0}, {0, 0, 0, 0}};
    int n0 = w * 16;
    #pragma unroll
    for (int kk = 0; kk < 8; kk++) {
      uint32_t off = (n0 + lrow) * PAD_STR + kk * 32 + lhi * 16;
      uint32_t bh[4];
      LDSM4(bh, sb + OFF_KH + off);
      MMAF16(acc[0], aH[kk], bh[0], bh[2]);
      MMAF16(acc[1], aH[kk], bh[1], bh[3]);
      MMAF16(acc[0], aL[kk], bh[0], bh[2]);
      MMAF16(acc[1], aL[kk], bh[1], bh[3]);
    }
    int r0 = lane >> 2, c0 = (lane & 3) * 2;
    int qs0 = qb * 16;
    #pragma unroll
    for (int nt = 0; nt < 2; nt++) {
      int col = kc + n0 + nt * 8 + c0;
      s_scores[r0 * SCW + col]           = (col     <= qs0 + r0)     ? acc[nt][0] * SC : -1e30f;
      s_scores[r0 * SCW + col + 1]       = (col + 1 <= qs0 + r0)     ? acc[nt][1] * SC : -1e30f;
      s_scores[(r0 + 8) * SCW + col]     = (col     <= qs0 + r0 + 8) ? acc[nt][2] * SC : -1e30f;
      s_scores[(r0 + 8) * SCW + col + 1] = (col + 1 <= qs0 + r0 + 8) ? acc[nt][3] * SC : -1e30f;
    }
  }
  __syncthreads();

  // ---- softmax stats ----
  {
    int qi = tid >> 4, r = tid & 15;
    float m = -1e30f;
    for (int j = r; j < kend; j += 16) m = fmaxf(m, s_scores[qi * SCW + j]);
    #pragma unroll
    for (int o = 8; o; o >>= 1) m = fmaxf(m, __shfl_xor_sync(0xffffffffu, m, o));
    float s = 0.f;
    for (int j = r; j < kend; j += 16) s += __expf(s_scores[qi * SCW + j] - m);
    #pragma unroll
    for (int o = 8; o; o >>= 1) s += __shfl_xor_sync(0xffffffffu, s, o);
    if (r == 0) { s_red[qi] = m; s_red[16 + qi] = 1.0f / s; }
  }
  __syncthreads();

  // ---- attn prob output ----
  if (write_attn) {
    float* ab = attn_out + ((size_t)(b * NH + h) * SEQ + (size_t)qb * 16) * SEQ;
    for (int idx = tid; idx < 16 * 512; idx += 256) {
      int qi = idx >> 9, j4 = (idx & 511) * 4;
      float m = s_red[qi], inv = s_red[16 + qi];
      float4 p = {0, 0, 0, 0};
      if (j4 < kend) {
        p.x = __expf(s_scores[qi * SCW + j4] - m) * inv;
        if (j4 + 1 < kend) p.y = __expf(s_scores[qi * SCW + j4 + 1] - m) * inv;
        if (j4 + 2 < kend) p.z = __expf(s_scores[qi * SCW + j4 + 2] - m) * inv;
        if (j4 + 3 < kend) p.w = __expf(s_scores[qi * SCW + j4 + 3] - m) * inv;
      }
      *(float4*)(ab + (size_t)qi * SEQ + j4) = p;
    }
  }

  // ---- AV (2-term: Ph·Vh + Ph·Vl) ----
  float oacc[2][4] = {{0, 0, 0, 0}, {0, 0, 0, 0}};
  for (int kc = 0; kc < kend; kc += 128) {
    __syncthreads();
    for (int idx = tid; idx < 128 * 16; idx += 256) {
      int j = idx >> 4, g = idx & 15;
      uint4 vh = {0, 0, 0, 0}, vl = {0, 0, 0, 0};
      if (kc + j < kend) {
        size_t go = ((size_t)(b * SEQ + kc + j) * NKV + hk) * HDIM + g * 8;
        vh = *(const uint4*)(g_vbh + go);
        vl = *(const uint4*)(g_vbl + go);
      }
      *(uint4*)(smc + OFF_KH + j * PAD_STR + g * 16) = vh;
      *(uint4*)(smc + OFF_KL + j * PAD_STR + g * 16) = vl;
    }
    for (int idx = tid; idx < 16 * 64; idx += 256) {
      int r = idx >> 6, c2 = (idx & 63) * 2;
      float m = s_red[r], inv = s_red[16 + r];
      float p0 = 0.f, p1 = 0.f;
      if (kc + c2 < kend)     p0 = __expf(s_scores[r * SCW + kc + c2] - m) * inv;
      if (kc + c2 + 1 < kend) p1 = __expf(s_scores[r * SCW + kc + c2 + 1] - m) * inv;
      __half2 hh;
      hh.x = __float2half_rn(p0);
      hh.y = __float2half_rn(p1);
      *(__half2*)(smc + OFF_PH + r * PAD_STR + c2 * 2) = hh;
    }
    __syncthreads();

    #pragma unroll
    for (int kk = 0; kk < 8; kk++) {
      uint32_t pOff = lrow * PAD_STR + kk * 32 + lhi * 16;
      uint32_t ph[4];
      LDSM4(ph, sb + OFF_PH + pOff);
      uint32_t vOff = (kk * 16 + lrow) * PAD_STR + w * 32 + lhi * 16;
      uint32_t vh[4], vl[4];
      LDSM4T(vh, sb + OFF_KH + vOff);
      LDSM4T(vl, sb + OFF_KL + vOff);
      MMAF16(oacc[0], ph, vh[0], vh[1]);
      MMAF16(oacc[1], ph, vh[2], vh[3]);
      MMAF16(oacc[0], ph, vl[0], vl[1]);
      MMAF16(oacc[1], ph, vl[2], vl[3]);
    }
  }

  // epilogue: split ctx fp16 [tok, H*HD]
  {
    int r0 = lane >> 2, c0 = (lane & 3) * 2;
    #pragma unroll
    for (int nt = 0; nt < 2; nt++) {
      int col = w * 16 + nt * 8 + c0;
      #pragma unroll
      for (int half = 0; half < 2; half++) {
        __half h0, l0, h1, l1;
        split16(oacc[nt][2 * half], h0, l0);
        split16(oacc[nt][2 * half + 1], h1, l1);
        __half2 hh; hh.x = h0; hh.y = h1;
        __half2 ll; ll.x = l0; ll.y = l1;
        size_t o = ((size_t)(b * SEQ + qb * 16 + r0 + half * 8)) * DMODEL
                 + h * HDIM + col;
        *(__half2*)(g_cth + o) = hh;
        *(__half2*)(g_ctl + o) = ll;
      }
    }
  }
}

// ---------------------------------------------------------------------------
extern "C" void kernel_launch(void* const* d_in, const int* in_sizes, int n_in,
                              void* d_out, int out_size) {
  const float* x  = (const float*)d_in[0];
  const float* Wq = (const float*)d_in[1];
  const float* Wk = (const float*)d_in[2];
  const float* Wv = (const float*)d_in[3];
  const float* Wo = (const float*)d_in[4];
  float* out = (float*)d_out;
  float* attn = out + (size_t)NTOK * DMODEL;
  long long need = (long long)NTOK * DMODEL + (long long)BATCH * NH * SEQ * SEQ;
  int write_attn = ((long long)out_size >= need) ? 1 : 0;

  float *gq, *gk;
  __half *xh, *xl, *cth, *ctl, *vbh, *vbl;
  __half *wqh, *wql, *wkh, *wkl, *wvh, *wvl, *woh, *wol;
  cudaGetSymbolAddress((void**)&gq, g_q);
  cudaGetSymbolAddress((void**)&gk, g_k);
  cudaGetSymbolAddress((void**)&xh, g_xh);
  cudaGetSymbolAddress((void**)&xl, g_xl);
  cudaGetSymbolAddress((void**)&cth, g_cth);
  cudaGetSymbolAddress((void**)&ctl, g_ctl);
  cudaGetSymbolAddress((void**)&vbh, g_vbh);
  cudaGetSymbolAddress((void**)&vbl, g_vbl);
  cudaGetSymbolAddress((void**)&wqh, g_wqh);
  cudaGetSymbolAddress((void**)&wql, g_wql);
  cudaGetSymbolAddress((void**)&wkh, g_wkh);
  cudaGetSymbolAddress((void**)&wkl, g_wkl);
  cudaGetSymbolAddress((void**)&wvh, g_wvh);
  cudaGetSymbolAddress((void**)&wvl, g_wvl);
  cudaGetSymbolAddress((void**)&woh, g_woh);
  cudaGetSymbolAddress((void**)&wol, g_wol);

  cudaFuncSetAttribute(gemm_kernel<3>, cudaFuncAttributeMaxDynamicSharedMemorySize,
                       GEMM_SMEM);
  cudaFuncSetAttribute(gemm_kernel<2>, cudaFuncAttributeMaxDynamicSharedMemorySize,
                       GEMM_SMEM);
  cudaFuncSetAttribute(attn_mma_kernel, cudaFuncAttributeMaxDynamicSharedMemorySize,
                       ATTN_SMEM);

  {
    int n = NTOK * DMODEL;
    split_kernel<<<(n + 255) / 256, 256>>>(x, xh, xl, n);
  }
  wsplit_kernel<<<dim3((NH*HDIM)/32, DMODEL/32), dim3(32, 8)>>>(Wq, wqh, wql, DMODEL, NH*HDIM);
  wsplit_kernel<<<dim3((NKV*HDIM)/32, DMODEL/32), dim3(32, 8)>>>(Wk, wkh, wkl, DMODEL, NKV*HDIM);
  wsplit_kernel<<<dim3((NKV*HDIM)/32, DMODEL/32), dim3(32, 8)>>>(Wv, wvh, wvl, DMODEL, NKV*HDIM);
  wsplit_kernel<<<dim3(DMODEL/32, DMODEL/32), dim3(32, 8)>>>(Wo, woh, wol, DMODEL, DMODEL);

  // Q/K projections: 2-term (x corrected, W hi only)
  gemm_kernel<2><<<dim3((NH*HDIM)/GBN, NTOK/GBM), 256, GEMM_SMEM>>>(
      xh, xl, wqh, wql, gq, nullptr, nullptr, DMODEL, NH*HDIM);
  gemm_kernel<2><<<dim3((NKV*HDIM)/GBN, NTOK/GBM), 256, GEMM_SMEM>>>(
      xh, xl, wkh, wkl, gk, nullptr, nullptr, DMODEL, NKV*HDIM);
  // V projection: 2-term, writes split fp16 V directly
  gemm_kernel<2><<<dim3((NKV*HDIM)/GBN, NTOK/GBM), 256, GEMM_SMEM>>>(
      xh, xl, wvh, wvl, nullptr, vbh, vbl, DMODEL, NKV*HDIM);

  rope_norm_kernel<<<dim3(NTOK, NH + NKV), 64>>>();

  attn_mma_kernel<<<dim3(SEQ / 16, NH, BATCH), 256, ATTN_SMEM>>>(attn, write_attn);

  // output projection: 2-term
  gemm_kernel<2><<<dim3(DMODEL/GBN, NTOK/GBM), 256, GEMM_SMEM>>>(
      cth, ctl, woh, wol, out, nullptr, nullptr, DMODEL, DMODEL);
}

// round 14
// speedup vs baseline: 3.0599x; 1.1653x over previous
#include <cuda_runtime.h>
#include <cuda_fp16.h>
#include <math.h>
#include <stdint.h>

#define NH     16
#define NKV    4
#define HDIM   128
#define BATCH  2
#define SEQ    2048
#define DMODEL 2048
#define NTOK   (BATCH*SEQ)

// ---------------------------------------------------------------------------
// scratch
// ---------------------------------------------------------------------------
static __device__ float g_q[NTOK * NH * HDIM];
static __device__ float g_k[NTOK * NKV * HDIM];

static __device__ __half g_qh[NTOK * NH * HDIM];
static __device__ __half g_ql[NTOK * NH * HDIM];
static __device__ __half g_kbh[NTOK * NKV * HDIM];
static __device__ __half g_vbh[NTOK * NKV * HDIM];

static __device__ __half g_xh[NTOK * DMODEL];
static __device__ __half g_xl[NTOK * DMODEL];
static __device__ __half g_cth[NTOK * DMODEL];
static __device__ __half g_wqh[DMODEL * (NH*HDIM)];
static __device__ __half g_wkh[DMODEL * (NKV*HDIM)];
static __device__ __half g_wvh[DMODEL * (NKV*HDIM)];
static __device__ __half g_woh[DMODEL * DMODEL];

// ---------------------------------------------------------------------------
// helpers
// ---------------------------------------------------------------------------
__device__ __forceinline__ uint32_t smem_u32(const void* p) {
  uint32_t a;
  asm("{ .reg .u64 t; cvta.to.shared.u64 t, %1; cvt.u32.u64 %0, t; }" : "=r"(a) : "l"(p));
  return a;
}

#define LDSM4(R, addr)                                                        \
  asm volatile("ldmatrix.sync.aligned.m8n8.x4.shared.b16 {%0,%1,%2,%3}, [%4];"\
    : "=r"((R)[0]), "=r"((R)[1]), "=r"((R)[2]), "=r"((R)[3]) : "r"(addr))

#define LDSM4T(R, addr)                                                       \
  asm volatile("ldmatrix.sync.aligned.m8n8.x4.trans.shared.b16 {%0,%1,%2,%3}, [%4];"\
    : "=r"((R)[0]), "=r"((R)[1]), "=r"((R)[2]), "=r"((R)[3]) : "r"(addr))

#define MMAF16(D, A, b0v, b1v)                                                \
  asm volatile("mma.sync.aligned.m16n8k16.row.col.f32.f16.f16.f32 "           \
    "{%0,%1,%2,%3}, {%4,%5,%6,%7}, {%8,%9}, {%0,%1,%2,%3};"                   \
    : "+f"((D)[0]), "+f"((D)[1]), "+f"((D)[2]), "+f"((D)[3])                  \
    : "r"((A)[0]), "r"((A)[1]), "r"((A)[2]), "r"((A)[3]), "r"(b0v), "r"(b1v))

#define CP_ASYNC16(dst, src) \
  asm volatile("cp.async.cg.shared.global [%0], [%1], 16;" :: "r"(dst), "l"(src))
#define CP_COMMIT() asm volatile("cp.async.commit_group;")

__device__ __forceinline__ void split16(float v, __half& h, __half& l) {
  h = __float2half_rn(v);
  l = __float2half_rn(v - __half2float(h));
}

// ---------------------------------------------------------------------------
// split fp32 -> fp16 hi/lo
// ---------------------------------------------------------------------------
__global__ void __launch_bounds__(256) split_kernel(const float* __restrict__ src,
    __half* __restrict__ hi, __half* __restrict__ lo, int n) {
  int i = blockIdx.x * 256 + threadIdx.x;
  if (i < n) {
    __half h, l;
    split16(src[i], h, l);
    hi[i] = h; lo[i] = l;
  }
}

// W [K,N] fp32 -> transposed fp16 hi [N,K] (hi plane only)
__global__ void __launch_bounds__(256) wsplit_kernel(const float* __restrict__ W,
    __half* __restrict__ th, int K, int N) {
  __shared__ float t[32][33];
  int n0 = blockIdx.x * 32, k0 = blockIdx.y * 32;
  int x = threadIdx.x, y = threadIdx.y;  // 32 x 8
  #pragma unroll
  for (int i = 0; i < 4; i++)
    t[y * 4 + i][x] = W[(size_t)(k0 + y * 4 + i) * N + n0 + x];
  __syncthreads();
  #pragma unroll
  for (int i = 0; i < 4; i++) {
    int n = n0 + y * 4 + i;
    th[(size_t)n * K + k0 + x] = __float2half_rn(t[x][y * 4 + i]);
  }
}

// ---------------------------------------------------------------------------
// mma.sync GEMM, fp16 split: C = A @ B^T (B stored [N,K], hi plane only).
// TERMS=2: AhBh + AlBh. TERMS=1: AhBh.
// Epilogue: Cf -> fp32; else Ch (+ optional Cl split).
// 2-stage, 80KB smem, 2 CTAs/SM.
// ---------------------------------------------------------------------------
#define GBM 128
#define GBN 128
#define GBK 32
#define RSTRIDE 80
#define TILE_BYTES (128 * RSTRIDE)
#define STG_BYTES (4 * TILE_BYTES)
#define GEMM_SMEM (2 * STG_BYTES)

template <int TERMS>
__global__ void __launch_bounds__(256, 2) gemm_kernel(
    const __half* __restrict__ Ah, const __half* __restrict__ Al,
    const __half* __restrict__ Bh,
    float* __restrict__ Cf, __half* __restrict__ Ch,
    __half* __restrict__ Cl, int K, int N) {
  extern __shared__ char smem[];
  uint32_t sbase = smem_u32(smem);
  int tid = threadIdx.x;
  int wid = tid >> 5, lane = tid & 31;
  int wm = wid >> 1, wn = wid & 1;
  int bm = blockIdx.y * GBM, bn = blockIdx.x * GBN;
  int nc = K / GBK;

  const __half* srcs[3] = {Ah, Al, Bh};
  int rbase[3] = {bm, bm, bn};

  auto load_chunk = [&](int c, int buf) {
    int k0 = c * GBK;
    #pragma unroll
    for (int i = 0; i < 6; i++) {
      if (TERMS == 1 && (i == 2 || i == 3)) continue;   // skip Al tile
      int idx = tid + i * 256;
      int t = i >> 1;
      int r = (idx >> 2) & 127;
      int g = idx & 3;
      uint32_t dst = sbase + buf * STG_BYTES + t * TILE_BYTES + r * RSTRIDE + g * 16;
      const __half* src = srcs[t] + (size_t)(rbase[t] + r) * K + k0 + g * 8;
      CP_ASYNC16(dst, src);
    }
    CP_COMMIT();
  };

  float acc[2][8][4];
  #pragma unroll
  for (int mi = 0; mi < 2; mi++)
    #pragma unroll
    for (int ni = 0; ni < 8; ni++)
      #pragma unroll
      for (int j = 0; j < 4; j++) acc[mi][ni][j] = 0.f;

  load_chunk(0, 0);
  int lrow = lane & 15, lk8 = (lane >> 4) * 8;

  for (int c = 0; c < nc; c++) {
    if (c + 1 < nc) {
      load_chunk(c + 1, (c + 1) & 1);
      asm volatile("cp.async.wait_group 1;");
    } else {
      asm volatile("cp.async.wait_group 0;");
    }
    __syncthreads();

    uint32_t b0 = sbase + (c & 1) * STG_BYTES;
    uint32_t aHs = b0, aLs = b0 + TILE_BYTES;
    uint32_t bHs = b0 + 2 * TILE_BYTES;

    #pragma unroll
    for (int kk = 0; kk < GBK; kk += 16) {
      uint32_t ah[2][4], al[2][4];
      uint32_t aoff = (uint32_t)(wm * 32 + lrow) * RSTRIDE + (kk + lk8) * 2;
      LDSM4(ah[0], aHs + aoff);
      LDSM4(ah[1], aHs + aoff + 16 * RSTRIDE);
      if (TERMS == 2) {
        LDSM4(al[0], aLs + aoff);
        LDSM4(al[1], aLs + aoff + 16 * RSTRIDE);
      }
      #pragma unroll
      for (int p = 0; p < 4; p++) {
        uint32_t boff = (uint32_t)(wn * 64 + p * 16 + lrow) * RSTRIDE + (kk + lk8) * 2;
        uint32_t h[4];
        LDSM4(h, bHs + boff);
        #pragma unroll
        for (int mi = 0; mi < 2; mi++) {
          MMAF16(acc[mi][2 * p],     ah[mi], h[0], h[2]);
          MMAF16(acc[mi][2 * p + 1], ah[mi], h[1], h[3]);
          if (TERMS == 2) {
            MMAF16(acc[mi][2 * p],     al[mi], h[0], h[2]);
            MMAF16(acc[mi][2 * p + 1], al[mi], h[1], h[3]);
          }
        }
      }
    }
    __syncthreads();
  }

  int gid = lane >> 2, cid = lane & 3;
  if (Cf) {
    #pragma unroll
    for (int mi = 0; mi < 2; mi++)
      #pragma unroll
      for (int ni = 0; ni < 8; ni++) {
        int row = bm + wm * 32 + mi * 16 + gid;
        int col = bn + wn * 64 + ni * 8 + cid * 2;
        *(float2*)(Cf + (size_t)row * N + col) =
            make_float2(acc[mi][ni][0], acc[mi][ni][1]);
        *(float2*)(Cf + (size_t)(row + 8) * N + col) =
            make_float2(acc[mi][ni][2], acc[mi][ni][3]);
      }
  } else {
    #pragma unroll
    for (int mi = 0; mi < 2; mi++)
      #pragma unroll
      for (int ni = 0; ni < 8; ni++) {
        int row = bm + wm * 32 + mi * 16 + gid;
        int col = bn + wn * 64 + ni * 8 + cid * 2;
        #pragma unroll
        for (int half = 0; half < 2; half++) {
          float v0 = acc[mi][ni][2 * half], v1 = acc[mi][ni][2 * half + 1];
          __half2 hh;
          hh.x = __float2half_rn(v0);
          hh.y = __float2half_rn(v1);
          size_t o = (size_t)(row + half * 8) * N + col;
          *(__half2*)(Ch + o) = hh;
          if (Cl) {
            __half2 ll;
            ll.x = __float2half_rn(v0 - __half2float(hh.x));
            ll.y = __float2half_rn(v1 - __half2float(hh.y));
            *(__half2*)(Cl + o) = ll;
          }
        }
      }
  }
}

// ---------------------------------------------------------------------------
// RoPE + L2 norm: q -> split fp16 (hi+lo); k -> hi only.
// ---------------------------------------------------------------------------
__global__ void __launch_bounds__(64) rope_norm_kernel() {
  int tok = blockIdx.x;
  int r = blockIdx.y;
  size_t off = (r < NH) ? ((size_t)tok * NH + r) * HDIM
                        : ((size_t)tok * NKV + (r - NH)) * HDIM;
  const float* base = (r < NH) ? g_q + off : g_k + off;
  int pos = tok & (SEQ - 1);
  int i = threadIdx.x;  // pair 0..63
  float t0 = base[2 * i], t1 = base[2 * i + 1];
  float inv = exp2f((float)(2 * i) * (-13.287712379549449f / 128.0f));
  float ang = (float)pos * inv;
  float sn, cs;
  sincosf(ang, &sn, &cs);
  float r0 = t0 * cs - t1 * sn;
  float r1 = t0 * sn + t1 * cs;
  float ss = r0 * r0 + r1 * r1;
  #pragma unroll
  for (int o = 16; o; o >>= 1) ss += __shfl_xor_sync(0xffffffffu, ss, o);
  __shared__ float part[2];
  if ((i & 31) == 0) part[i >> 5] = ss;
  __syncthreads();
  float sc = rsqrtf((part[0] + part[1]) * (1.0f / 128.0f) + 1e-6f);
  float v0 = r0 * sc, v1 = r1 * sc;
  if (r < NH) {
    __half h0, l0, h1, l1;
    split16(v0, h0, l0);
    split16(v1, h1, l1);
    g_qh[off + 2 * i] = h0; g_qh[off + 2 * i + 1] = h1;
    g_ql[off + 2 * i] = l0; g_ql[off + 2 * i + 1] = l1;
  } else {
    g_kbh[off + 2 * i] = __float2half_rn(v0);
    g_kbh[off + 2 * i + 1] = __float2half_rn(v1);
  }
}

// ---------------------------------------------------------------------------
// MMA attention: QK 2-term (Qh·Kh + Ql·Kh), AV 1-term (Ph·Vh).
// ctx written as single fp16 plane.
// ---------------------------------------------------------------------------
#define SCW 2056
#define PAD_STR 272
#define OFF_QH 131584
#define OFF_QL (OFF_QH + 16*PAD_STR)
#define OFF_KH (OFF_QL + 16*PAD_STR)
#define OFF_PH (OFF_KH + 128*PAD_STR)
#define OFF_RED (OFF_PH + 16*PAD_STR)
#define ATTN_SMEM (OFF_RED + 128)

__global__ void __launch_bounds__(256, 1) attn_mma_kernel(
    float* __restrict__ attn_out, int write_attn) {
  extern __shared__ char smc[];
  float* s_scores = (float*)smc;
  float* s_red = (float*)(smc + OFF_RED);
  uint32_t sb = smem_u32(smc);

  int qb = gridDim.x - 1 - blockIdx.x;
  int h = blockIdx.y, b = blockIdx.z;
  int hk = h >> 2;
  int tid = threadIdx.x, w = tid >> 5, lane = tid & 31;
  int kend = qb * 16 + 16;
  const float SC = 0.08838834764831845f;
  int lrow = lane & 15, lhi = lane >> 4;

  {
    int r = tid >> 4, g = tid & 15;
    size_t go = ((size_t)(b * SEQ + qb * 16 + r) * NH + h) * HDIM + g * 8;
    *(uint4*)(smc + OFF_QH + r * PAD_STR + g * 16) = *(const uint4*)(g_qh + go);
    *(uint4*)(smc + OFF_QL + r * PAD_STR + g * 16) = *(const uint4*)(g_ql + go);
  }
  __syncthreads();

  uint32_t aH[8][4], aL[8][4];
  #pragma unroll
  for (int kk = 0; kk < 8; kk++) {
    uint32_t off = lrow * PAD_STR + kk * 32 + lhi * 16;
    LDSM4(aH[kk], sb + OFF_QH + off);
    LDSM4(aL[kk], sb + OFF_QL + off);
  }

  // ---- scores (2-term; K-hi only) ----
  for (int kc = 0; kc < kend; kc += 128) {
    __syncthreads();
    for (int idx = tid; idx < 128 * 16; idx += 256) {
      int j = idx >> 4, g = idx & 15;
      uint4 vh = {0, 0, 0, 0};
      if (kc + j < kend) {
        size_t go = ((size_t)(b * SEQ + kc + j) * NKV + hk) * HDIM + g * 8;
        vh = *(const uint4*)(g_kbh + go);
      }
      *(uint4*)(smc + OFF_KH + j * PAD_STR + g * 16) = vh;
    }
    __syncthreads();

    float acc[2][4] = {{0, 0, 0, 0}, {0, 0, 0, 0}};
    int n0 = w * 16;
    #pragma unroll
    for (int kk = 0; kk < 8; kk++) {
      uint32_t off = (n0 + lrow) * PAD_STR + kk * 32 + lhi * 16;
      uint32_t bh[4];
      LDSM4(bh, sb + OFF_KH + off);
      MMAF16(acc[0], aH[kk], bh[0], bh[2]);
      MMAF16(acc[1], aH[kk], bh[1], bh[3]);
      MMAF16(acc[0], aL[kk], bh[0], bh[2]);
      MMAF16(acc[1], aL[kk], bh[1], bh[3]);
    }
    int r0 = lane >> 2, c0 = (lane & 3) * 2;
    int qs0 = qb * 16;
    #pragma unroll
    for (int nt = 0; nt < 2; nt++) {
      int col = kc + n0 + nt * 8 + c0;
      s_scores[r0 * SCW + col]           = (col     <= qs0 + r0)     ? acc[nt][0] * SC : -1e30f;
      s_scores[r0 * SCW + col + 1]       = (col + 1 <= qs0 + r0)     ? acc[nt][1] * SC : -1e30f;
      s_scores[(r0 + 8) * SCW + col]     = (col     <= qs0 + r0 + 8) ? acc[nt][2] * SC : -1e30f;
      s_scores[(r0 + 8) * SCW + col + 1] = (col + 1 <= qs0 + r0 + 8) ? acc[nt][3] * SC : -1e30f;
    }
  }
  __syncthreads();

  // ---- softmax stats ----
  {
    int qi = tid >> 4, r = tid & 15;
    float m = -1e30f;
    for (int j = r; j < kend; j += 16) m = fmaxf(m, s_scores[qi * SCW + j]);
    #pragma unroll
    for (int o = 8; o; o >>= 1) m = fmaxf(m, __shfl_xor_sync(0xffffffffu, m, o));
    float s = 0.f;
    for (int j = r; j < kend; j += 16) s += __expf(s_scores[qi * SCW + j] - m);
    #pragma unroll
    for (int o = 8; o; o >>= 1) s += __shfl_xor_sync(0xffffffffu, s, o);
    if (r == 0) { s_red[qi] = m; s_red[16 + qi] = 1.0f / s; }
  }
  __syncthreads();

  // ---- attn prob output ----
  if (write_attn) {
    float* ab = attn_out + ((size_t)(b * NH + h) * SEQ + (size_t)qb * 16) * SEQ;
    for (int idx = tid; idx < 16 * 512; idx += 256) {
      int qi = idx >> 9, j4 = (idx & 511) * 4;
      float m = s_red[qi], inv = s_red[16 + qi];
      float4 p = {0, 0, 0, 0};
      if (j4 < kend) {
        p.x = __expf(s_scores[qi * SCW + j4] - m) * inv;
        if (j4 + 1 < kend) p.y = __expf(s_scores[qi * SCW + j4 + 1] - m) * inv;
        if (j4 + 2 < kend) p.z = __expf(s_scores[qi * SCW + j4 + 2] - m) * inv;
        if (j4 + 3 < kend) p.w = __expf(s_scores[qi * SCW + j4 + 3] - m) * inv;
      }
      *(float4*)(ab + (size_t)qi * SEQ + j4) = p;
    }
  }

  // ---- AV (1-term: Ph·Vh) ----
  float oacc[2][4] = {{0, 0, 0, 0}, {0, 0, 0, 0}};
  for (int kc = 0; kc < kend; kc += 128) {
    __syncthreads();
    for (int idx = tid; idx < 128 * 16; idx += 256) {
      int j = idx >> 4, g = idx & 15;
      uint4 vh = {0, 0, 0, 0};
      if (kc + j < kend) {
        size_t go = ((size_t)(b * SEQ + kc + j) * NKV + hk) * HDIM + g * 8;
        vh = *(const uint4*)(g_vbh + go);
      }
      *(uint4*)(smc + OFF_KH + j * PAD_STR + g * 16) = vh;
    }
    for (int idx = tid; idx < 16 * 64; idx += 256) {
      int r = idx >> 6, c2 = (idx & 63) * 2;
      float m = s_red[r], inv = s_red[16 + r];
      float p0 = 0.f, p1 = 0.f;
      if (kc + c2 < kend)     p0 = __expf(s_scores[r * SCW + kc + c2] - m) * inv;
      if (kc + c2 + 1 < kend) p1 = __expf(s_scores[r * SCW + kc + c2 + 1] - m) * inv;
      __half2 hh;
      hh.x = __float2half_rn(p0);
      hh.y = __float2half_rn(p1);
      *(__half2*)(smc + OFF_PH + r * PAD_STR + c2 * 2) = hh;
    }
    __syncthreads();

    #pragma unroll
    for (int kk = 0; kk < 8; kk++) {
      uint32_t pOff = lrow * PAD_STR + kk * 32 + lhi * 16;
      uint32_t ph[4];
      LDSM4(ph, sb + OFF_PH + pOff);
      uint32_t vOff = (kk * 16 + lrow) * PAD_STR + w * 32 + lhi * 16;
      uint32_t vh[4];
      LDSM4T(vh, sb + OFF_KH + vOff);
      MMAF16(oacc[0], ph, vh[0], vh[1]);
      MMAF16(oacc[1], ph, vh[2], vh[3]);
    }
  }

  // epilogue: ctx fp16 hi plane [tok, H*HD]
  {
    int r0 = lane >> 2, c0 = (lane & 3) * 2;
    #pragma unroll
    for (int nt = 0; nt < 2; nt++) {
      int col = w * 16 + nt * 8 + c0;
      #pragma unroll
      for (int half = 0; half < 2; half++) {
        __half2 hh;
        hh.x = __float2half_rn(oacc[nt][2 * half]);
        hh.y = __float2half_rn(oacc[nt][2 * half + 1]);
        size_t o = ((size_t)(b * SEQ + qb * 16 + r0 + half * 8)) * DMODEL
                 + h * HDIM + col;
        *(__half2*)(g_cth + o) = hh;
      }
    }
  }
}

// ---------------------------------------------------------------------------
extern "C" void kernel_launch(void* const* d_in, const int* in_sizes, int n_in,
                              void* d_out, int out_size) {
  const float* x  = (const float*)d_in[0];
  const float* Wq = (const float*)d_in[1];
  const float* Wk = (const float*)d_in[2];
  const float* Wv = (const float*)d_in[3];
  const float* Wo = (const float*)d_in[4];
  float* out = (float*)d_out;
  float* attn = out + (size_t)NTOK * DMODEL;
  long long need = (long long)NTOK * DMODEL + (long long)BATCH * NH * SEQ * SEQ;
  int write_attn = ((long long)out_size >= need) ? 1 : 0;

  float *gq, *gk;
  __half *xh, *xl, *cth, *vbh;
  __half *wqh, *wkh, *wvh, *woh;
  cudaGetSymbolAddress((void**)&gq, g_q);
  cudaGetSymbolAddress((void**)&gk, g_k);
  cudaGetSymbolAddress((void**)&xh, g_xh);
  cudaGetSymbolAddress((void**)&xl, g_xl);
  cudaGetSymbolAddress((void**)&cth, g_cth);
  cudaGetSymbolAddress((void**)&vbh, g_vbh);
  cudaGetSymbolAddress((void**)&wqh, g_wqh);
  cudaGetSymbolAddress((void**)&wkh, g_wkh);
  cudaGetSymbolAddress((void**)&wvh, g_wvh);
  cudaGetSymbolAddress((void**)&woh, g_woh);

  cudaFuncSetAttribute(gemm_kernel<2>, cudaFuncAttributeMaxDynamicSharedMemorySize,
                       GEMM_SMEM);
  cudaFuncSetAttribute(gemm_kernel<1>, cudaFuncAttributeMaxDynamicSharedMemorySize,
                       GEMM_SMEM);
  cudaFuncSetAttribute(attn_mma_kernel, cudaFuncAttributeMaxDynamicSharedMemorySize,
                       ATTN_SMEM);

  {
    int n = NTOK * DMODEL;
    split_kernel<<<(n + 255) / 256, 256>>>(x, xh, xl, n);
  }
  wsplit_kernel<<<dim3((NH*HDIM)/32, DMODEL/32), dim3(32, 8)>>>(Wq, wqh, DMODEL, NH*HDIM);
  wsplit_kernel<<<dim3((NKV*HDIM)/32, DMODEL/32), dim3(32, 8)>>>(Wk, wkh, DMODEL, NKV*HDIM);
  wsplit_kernel<<<dim3((NKV*HDIM)/32, DMODEL/32), dim3(32, 8)>>>(Wv, wvh, DMODEL, NKV*HDIM);
  wsplit_kernel<<<dim3(DMODEL/32, DMODEL/32), dim3(32, 8)>>>(Wo, woh, DMODEL, DMODEL);

  // Q/K projections: 2-term (x corrected, W hi only)
  gemm_kernel<2><<<dim3((NH*HDIM)/GBN, NTOK/GBM), 256, GEMM_SMEM>>>(
      xh, xl, wqh, gq, nullptr, nullptr, DMODEL, NH*HDIM);
  gemm_kernel<2><<<dim3((NKV*HDIM)/GBN, NTOK/GBM), 256, GEMM_SMEM>>>(
      xh, xl, wkh, gk, nullptr, nullptr, DMODEL, NKV*HDIM);
  // V projection: 2-term, writes fp16 hi plane only
  gemm_kernel<2><<<dim3((NKV*HDIM)/GBN, NTOK/GBM), 256, GEMM_SMEM>>>(
      xh, xl, wvh, nullptr, vbh, nullptr, DMODEL, NKV*HDIM);

  rope_norm_kernel<<<dim3(NTOK, NH + NKV), 64>>>();

  attn_mma_kernel<<<dim3(SEQ / 16, NH, BATCH), 256, ATTN_SMEM>>>(attn, write_attn);

  // output projection: 1-term (ctx hi x Wo hi)
  gemm_kernel<1><<<dim3(DMODEL/GBN, NTOK/GBM), 256, GEMM_SMEM>>>(
      cth, nullptr, woh, out, nullptr, nullptr, DMODEL, DMODEL);
}

// round 15
// speedup vs baseline: 3.6643x; 1.1975x over previous
#include <cuda_runtime.h>
#include <cuda_fp16.h>
#include <math.h>
#include <stdint.h>

#define NH     16
#define NKV    4
#define HDIM   128
#define BATCH  2
#define SEQ    2048
#define DMODEL 2048
#define NTOK   (BATCH*SEQ)

// ---------------------------------------------------------------------------
// scratch
// ---------------------------------------------------------------------------
static __device__ float g_q[NTOK * NH * HDIM];
static __device__ float g_k[NTOK * NKV * HDIM];

static __device__ __half g_qh[NTOK * NH * HDIM];
static __device__ __half g_kbh[NTOK * NKV * HDIM];
static __device__ __half g_vbh[NTOK * NKV * HDIM];

static __device__ __half g_xh[NTOK * DMODEL];
static __device__ __half g_cth[NTOK * DMODEL];
static __device__ __half g_wqh[DMODEL * (NH*HDIM)];
static __device__ __half g_wkh[DMODEL * (NKV*HDIM)];
static __device__ __half g_wvh[DMODEL * (NKV*HDIM)];
static __device__ __half g_woh[DMODEL * DMODEL];

// ---------------------------------------------------------------------------
// helpers
// ---------------------------------------------------------------------------
__device__ __forceinline__ uint32_t smem_u32(const void* p) {
  uint32_t a;
  asm("{ .reg .u64 t; cvta.to.shared.u64 t, %1; cvt.u32.u64 %0, t; }" : "=r"(a) : "l"(p));
  return a;
}

#define LDSM4(R, addr)                                                        \
  asm volatile("ldmatrix.sync.aligned.m8n8.x4.shared.b16 {%0,%1,%2,%3}, [%4];"\
    : "=r"((R)[0]), "=r"((R)[1]), "=r"((R)[2]), "=r"((R)[3]) : "r"(addr))

#define LDSM4T(R, addr)                                                       \
  asm volatile("ldmatrix.sync.aligned.m8n8.x4.trans.shared.b16 {%0,%1,%2,%3}, [%4];"\
    : "=r"((R)[0]), "=r"((R)[1]), "=r"((R)[2]), "=r"((R)[3]) : "r"(addr))

#define MMAF16(D, A, b0v, b1v)                                                \
  asm volatile("mma.sync.aligned.m16n8k16.row.col.f32.f16.f16.f32 "           \
    "{%0,%1,%2,%3}, {%4,%5,%6,%7}, {%8,%9}, {%0,%1,%2,%3};"                   \
    : "+f"((D)[0]), "+f"((D)[1]), "+f"((D)[2]), "+f"((D)[3])                  \
    : "r"((A)[0]), "r"((A)[1]), "r"((A)[2]), "r"((A)[3]), "r"(b0v), "r"(b1v))

#define CP_ASYNC16(dst, src) \
  asm volatile("cp.async.cg.shared.global [%0], [%1], 16;" :: "r"(dst), "l"(src))
#define CP_COMMIT() asm volatile("cp.async.commit_group;")

// ---------------------------------------------------------------------------
// fp32 -> fp16 convert
// ---------------------------------------------------------------------------
__global__ void __launch_bounds__(256) cvt_kernel(const float* __restrict__ src,
    __half* __restrict__ dst, int n4) {
  int i = blockIdx.x * 256 + threadIdx.x;
  if (i < n4) {
    float4 v = *(const float4*)(src + (size_t)i * 4);
    __half2 a, b;
    a.x = __float2half_rn(v.x); a.y = __float2half_rn(v.y);
    b.x = __float2half_rn(v.z); b.y = __float2half_rn(v.w);
    *(__half2*)(dst + (size_t)i * 4) = a;
    *(__half2*)(dst + (size_t)i * 4 + 2) = b;
  }
}

// W [K,N] fp32 -> transposed fp16 [N,K]
__global__ void __launch_bounds__(256) wcvt_kernel(const float* __restrict__ W,
    __half* __restrict__ th, int K, int N) {
  __shared__ float t[32][33];
  int n0 = blockIdx.x * 32, k0 = blockIdx.y * 32;
  int x = threadIdx.x, y = threadIdx.y;  // 32 x 8
  #pragma unroll
  for (int i = 0; i < 4; i++)
    t[y * 4 + i][x] = W[(size_t)(k0 + y * 4 + i) * N + n0 + x];
  __syncthreads();
  #pragma unroll
  for (int i = 0; i < 4; i++) {
    int n = n0 + y * 4 + i;
    th[(size_t)n * K + k0 + x] = __float2half_rn(t[x][y * 4 + i]);
  }
}

// ---------------------------------------------------------------------------
// mma.sync GEMM, pure fp16: C = A @ B^T (B stored [N,K]).
// 128x128 CTA, BK=32, 2-stage (20KB/stage), 2 CTAs/SM.
// Epilogue: Cf -> fp32, else Ch -> fp16.
// ---------------------------------------------------------------------------
#define GBM 128
#define GBN 128
#define GBK 32
#define RSTRIDE 80
#define TILE_BYTES (128 * RSTRIDE)
#define STG_BYTES (2 * TILE_BYTES)
#define GEMM_SMEM (2 * STG_BYTES)

__global__ void __launch_bounds__(256, 2) gemm_kernel(
    const __half* __restrict__ Ah, const __half* __restrict__ Bh,
    float* __restrict__ Cf, __half* __restrict__ Ch, int K, int N) {
  extern __shared__ char smem[];
  uint32_t sbase = smem_u32(smem);
  int tid = threadIdx.x;
  int wid = tid >> 5, lane = tid & 31;
  int wm = wid >> 1, wn = wid & 1;
  int bm = blockIdx.y * GBM, bn = blockIdx.x * GBN;
  int nc = K / GBK;

  auto load_chunk = [&](int c, int buf) {
    int k0 = c * GBK;
    #pragma unroll
    for (int i = 0; i < 4; i++) {
      int idx = tid + i * 256;
      int t = i >> 1;                   // 0 = A, 1 = B
      int r = (idx >> 2) & 127;
      int g = idx & 3;
      uint32_t dst = sbase + buf * STG_BYTES + t * TILE_BYTES + r * RSTRIDE + g * 16;
      const __half* src = (t ? Bh : Ah) + (size_t)((t ? bn : bm) + r) * K + k0 + g * 8;
      CP_ASYNC16(dst, src);
    }
    CP_COMMIT();
  };

  float acc[2][8][4];
  #pragma unroll
  for (int mi = 0; mi < 2; mi++)
    #pragma unroll
    for (int ni = 0; ni < 8; ni++)
      #pragma unroll
      for (int j = 0; j < 4; j++) acc[mi][ni][j] = 0.f;

  load_chunk(0, 0);
  int lrow = lane & 15, lk8 = (lane >> 4) * 8;

  for (int c = 0; c < nc; c++) {
    if (c + 1 < nc) {
      load_chunk(c + 1, (c + 1) & 1);
      asm volatile("cp.async.wait_group 1;");
    } else {
      asm volatile("cp.async.wait_group 0;");
    }
    __syncthreads();

    uint32_t b0 = sbase + (c & 1) * STG_BYTES;
    uint32_t aHs = b0, bHs = b0 + TILE_BYTES;

    #pragma unroll
    for (int kk = 0; kk < GBK; kk += 16) {
      uint32_t ah[2][4];
      uint32_t aoff = (uint32_t)(wm * 32 + lrow) * RSTRIDE + (kk + lk8) * 2;
      LDSM4(ah[0], aHs + aoff);
      LDSM4(ah[1], aHs + aoff + 16 * RSTRIDE);
      #pragma unroll
      for (int p = 0; p < 4; p++) {
        uint32_t boff = (uint32_t)(wn * 64 + p * 16 + lrow) * RSTRIDE + (kk + lk8) * 2;
        uint32_t h[4];
        LDSM4(h, bHs + boff);
        #pragma unroll
        for (int mi = 0; mi < 2; mi++) {
          MMAF16(acc[mi][2 * p],     ah[mi], h[0], h[2]);
          MMAF16(acc[mi][2 * p + 1], ah[mi], h[1], h[3]);
        }
      }
    }
    __syncthreads();
  }

  int gid = lane >> 2, cid = lane & 3;
  if (Cf) {
    #pragma unroll
    for (int mi = 0; mi < 2; mi++)
      #pragma unroll
      for (int ni = 0; ni < 8; ni++) {
        int row = bm + wm * 32 + mi * 16 + gid;
        int col = bn + wn * 64 + ni * 8 + cid * 2;
        *(float2*)(Cf + (size_t)row * N + col) =
            make_float2(acc[mi][ni][0], acc[mi][ni][1]);
        *(float2*)(Cf + (size_t)(row + 8) * N + col) =
            make_float2(acc[mi][ni][2], acc[mi][ni][3]);
      }
  } else {
    #pragma unroll
    for (int mi = 0; mi < 2; mi++)
      #pragma unroll
      for (int ni = 0; ni < 8; ni++) {
        int row = bm + wm * 32 + mi * 16 + gid;
        int col = bn + wn * 64 + ni * 8 + cid * 2;
        #pragma unroll
        for (int half = 0; half < 2; half++) {
          __half2 hh;
          hh.x = __float2half_rn(acc[mi][ni][2 * half]);
          hh.y = __float2half_rn(acc[mi][ni][2 * half + 1]);
          *(__half2*)(Ch + (size_t)(row + half * 8) * N + col) = hh;
        }
      }
  }
}

// ---------------------------------------------------------------------------
// RoPE + L2 norm: q/k -> fp16 hi only.
// ---------------------------------------------------------------------------
__global__ void __launch_bounds__(64) rope_norm_kernel() {
  int tok = blockIdx.x;
  int r = blockIdx.y;
  size_t off = (r < NH) ? ((size_t)tok * NH + r) * HDIM
                        : ((size_t)tok * NKV + (r - NH)) * HDIM;
  const float* base = (r < NH) ? g_q + off : g_k + off;
  __half* dst = (r < NH) ? g_qh + off : g_kbh + off;
  int pos = tok & (SEQ - 1);
  int i = threadIdx.x;  // pair 0..63
  float t0 = base[2 * i], t1 = base[2 * i + 1];
  float inv = exp2f((float)(2 * i) * (-13.287712379549449f / 128.0f));
  float ang = (float)pos * inv;
  float sn, cs;
  sincosf(ang, &sn, &cs);
  float r0 = t0 * cs - t1 * sn;
  float r1 = t0 * sn + t1 * cs;
  float ss = r0 * r0 + r1 * r1;
  #pragma unroll
  for (int o = 16; o; o >>= 1) ss += __shfl_xor_sync(0xffffffffu, ss, o);
  __shared__ float part[2];
  if ((i & 31) == 0) part[i >> 5] = ss;
  __syncthreads();
  float sc = rsqrtf((part[0] + part[1]) * (1.0f / 128.0f) + 1e-6f);
  __half2 hh;
  hh.x = __float2half_rn(r0 * sc);
  hh.y = __float2half_rn(r1 * sc);
  *(__half2*)(dst + 2 * i) = hh;
}

// ---------------------------------------------------------------------------
// MMA attention: QK 1-term, AV 1-term (pure fp16 operands, fp32 accum).
// ---------------------------------------------------------------------------
#define SCW 2056
#define PAD_STR 272
#define OFF_QH 131584
#define OFF_KH (OFF_QH + 16*PAD_STR)
#define OFF_PH (OFF_KH + 128*PAD_STR)
#define OFF_RED (OFF_PH + 16*PAD_STR)
#define ATTN_SMEM (OFF_RED + 128)

__global__ void __launch_bounds__(256, 1) attn_mma_kernel(
    float* __restrict__ attn_out, int write_attn) {
  extern __shared__ char smc[];
  float* s_scores = (float*)smc;
  float* s_red = (float*)(smc + OFF_RED);
  uint32_t sb = smem_u32(smc);

  int qb = gridDim.x - 1 - blockIdx.x;
  int h = blockIdx.y, b = blockIdx.z;
  int hk = h >> 2;
  int tid = threadIdx.x, w = tid >> 5, lane = tid & 31;
  int kend = qb * 16 + 16;
  const float SC = 0.08838834764831845f;
  int lrow = lane & 15, lhi = lane >> 4;

  {
    int r = tid >> 4, g = tid & 15;
    size_t go = ((size_t)(b * SEQ + qb * 16 + r) * NH + h) * HDIM + g * 8;
    *(uint4*)(smc + OFF_QH + r * PAD_STR + g * 16) = *(const uint4*)(g_qh + go);
  }
  __syncthreads();

  uint32_t aH[8][4];
  #pragma unroll
  for (int kk = 0; kk < 8; kk++) {
    uint32_t off = lrow * PAD_STR + kk * 32 + lhi * 16;
    LDSM4(aH[kk], sb + OFF_QH + off);
  }

  // ---- scores (1-term) ----
  for (int kc = 0; kc < kend; kc += 128) {
    __syncthreads();
    for (int idx = tid; idx < 128 * 16; idx += 256) {
      int j = idx >> 4, g = idx & 15;
      uint4 vh = {0, 0, 0, 0};
      if (kc + j < kend) {
        size_t go = ((size_t)(b * SEQ + kc + j) * NKV + hk) * HDIM + g * 8;
        vh = *(const uint4*)(g_kbh + go);
      }
      *(uint4*)(smc + OFF_KH + j * PAD_STR + g * 16) = vh;
    }
    __syncthreads();

    float acc[2][4] = {{0, 0, 0, 0}, {0, 0, 0, 0}};
    int n0 = w * 16;
    #pragma unroll
    for (int kk = 0; kk < 8; kk++) {
      uint32_t off = (n0 + lrow) * PAD_STR + kk * 32 + lhi * 16;
      uint32_t bh[4];
      LDSM4(bh, sb + OFF_KH + off);
      MMAF16(acc[0], aH[kk], bh[0], bh[2]);
      MMAF16(acc[1], aH[kk], bh[1], bh[3]);
    }
    int r0 = lane >> 2, c0 = (lane & 3) * 2;
    int qs0 = qb * 16;
    #pragma unroll
    for (int nt = 0; nt < 2; nt++) {
      int col = kc + n0 + nt * 8 + c0;
      s_scores[r0 * SCW + col]           = (col     <= qs0 + r0)     ? acc[nt][0] * SC : -1e30f;
      s_scores[r0 * SCW + col + 1]       = (col + 1 <= qs0 + r0)     ? acc[nt][1] * SC : -1e30f;
      s_scores[(r0 + 8) * SCW + col]     = (col     <= qs0 + r0 + 8) ? acc[nt][2] * SC : -1e30f;
      s_scores[(r0 + 8) * SCW + col + 1] = (col + 1 <= qs0 + r0 + 8) ? acc[nt][3] * SC : -1e30f;
    }
  }
  __syncthreads();

  // ---- softmax stats ----
  {
    int qi = tid >> 4, r = tid & 15;
    float m = -1e30f;
    for (int j = r; j < kend; j += 16) m = fmaxf(m, s_scores[qi * SCW + j]);
    #pragma unroll
    for (int o = 8; o; o >>= 1) m = fmaxf(m, __shfl_xor_sync(0xffffffffu, m, o));
    float s = 0.f;
    for (int j = r; j < kend; j += 16) s += __expf(s_scores[qi * SCW + j] - m);
    #pragma unroll
    for (int o = 8; o; o >>= 1) s += __shfl_xor_sync(0xffffffffu, s, o);
    if (r == 0) { s_red[qi] = m; s_red[16 + qi] = 1.0f / s; }
  }
  __syncthreads();

  // ---- attn prob output ----
  if (write_attn) {
    float* ab = attn_out + ((size_t)(b * NH + h) * SEQ + (size_t)qb * 16) * SEQ;
    for (int idx = tid; idx < 16 * 512; idx += 256) {
      int qi = idx >> 9, j4 = (idx & 511) * 4;
      float m = s_red[qi], inv = s_red[16 + qi];
      float4 p = {0, 0, 0, 0};
      if (j4 < kend) {
        p.x = __expf(s_scores[qi * SCW + j4] - m) * inv;
        if (j4 + 1 < kend) p.y = __expf(s_scores[qi * SCW + j4 + 1] - m) * inv;
        if (j4 + 2 < kend) p.z = __expf(s_scores[qi * SCW + j4 + 2] - m) * inv;
        if (j4 + 3 < kend) p.w = __expf(s_scores[qi * SCW + j4 + 3] - m) * inv;
      }
      *(float4*)(ab + (size_t)qi * SEQ + j4) = p;
    }
  }

  // ---- AV (1-term) ----
  float oacc[2][4] = {{0, 0, 0, 0}, {0, 0, 0, 0}};
  for (int kc = 0; kc < kend; kc += 128) {
    __syncthreads();
    for (int idx = tid; idx < 128 * 16; idx += 256) {
      int j = idx >> 4, g = idx & 15;
      uint4 vh = {0, 0, 0, 0};
      if (kc + j < kend) {
        size_t go = ((size_t)(b * SEQ + kc + j) * NKV + hk) * HDIM + g * 8;
        vh = *(const uint4*)(g_vbh + go);
      }
      *(uint4*)(smc + OFF_KH + j * PAD_STR + g * 16) = vh;
    }
    for (int idx = tid; idx < 16 * 64; idx += 256) {
      int r = idx >> 6, c2 = (idx & 63) * 2;
      float m = s_red[r], inv = s_red[16 + r];
      float p0 = 0.f, p1 = 0.f;
      if (kc + c2 < kend)     p0 = __expf(s_scores[r * SCW + kc + c2] - m) * inv;
      if (kc + c2 + 1 < kend) p1 = __expf(s_scores[r * SCW + kc + c2 + 1] - m) * inv;
      __half2 hh;
      hh.x = __float2half_rn(p0);
      hh.y = __float2half_rn(p1);
      *(__half2*)(smc + OFF_PH + r * PAD_STR + c2 * 2) = hh;
    }
    __syncthreads();

    #pragma unroll
    for (int kk = 0; kk < 8; kk++) {
      uint32_t pOff = lrow * PAD_STR + kk * 32 + lhi * 16;
      uint32_t ph[4];
      LDSM4(ph, sb + OFF_PH + pOff);
      uint32_t vOff = (kk * 16 + lrow) * PAD_STR + w * 32 + lhi * 16;
      uint32_t vh[4];
      LDSM4T(vh, sb + OFF_KH + vOff);
      MMAF16(oacc[0], ph, vh[0], vh[1]);
      MMAF16(oacc[1], ph, vh[2], vh[3]);
    }
  }

  // epilogue: ctx fp16 [tok, H*HD]
  {
    int r0 = lane >> 2, c0 = (lane & 3) * 2;
    #pragma unroll
    for (int nt = 0; nt < 2; nt++) {
      int col = w * 16 + nt * 8 + c0;
      #pragma unroll
      for (int half = 0; half < 2; half++) {
        __half2 hh;
        hh.x = __float2half_rn(oacc[nt][2 * half]);
        hh.y = __float2half_rn(oacc[nt][2 * half + 1]);
        size_t o = ((size_t)(b * SEQ + qb * 16 + r0 + half * 8)) * DMODEL
                 + h * HDIM + col;
        *(__half2*)(g_cth + o) = hh;
      }
    }
  }
}

// ---------------------------------------------------------------------------
extern "C" void kernel_launch(void* const* d_in, const int* in_sizes, int n_in,
                              void* d_out, int out_size) {
  const float* x  = (const float*)d_in[0];
  const float* Wq = (const float*)d_in[1];
  const float* Wk = (const float*)d_in[2];
  const float* Wv = (const float*)d_in[3];
  const float* Wo = (const float*)d_in[4];
  float* out = (float*)d_out;
  float* attn = out + (size_t)NTOK * DMODEL;
  long long need = (long long)NTOK * DMODEL + (long long)BATCH * NH * SEQ * SEQ;
  int write_attn = ((long long)out_size >= need) ? 1 : 0;

  float *gq, *gk;
  __half *xh, *cth, *vbh;
  __half *wqh, *wkh, *wvh, *woh;
  cudaGetSymbolAddress((void**)&gq, g_q);
  cudaGetSymbolAddress((void**)&gk, g_k);
  cudaGetSymbolAddress((void**)&xh, g_xh);
  cudaGetSymbolAddress((void**)&cth, g_cth);
  cudaGetSymbolAddress((void**)&vbh, g_vbh);
  cudaGetSymbolAddress((void**)&wqh, g_wqh);
  cudaGetSymbolAddress((void**)&wkh, g_wkh);
  cudaGetSymbolAddress((void**)&wvh, g_wvh);
  cudaGetSymbolAddress((void**)&woh, g_woh);

  cudaFuncSetAttribute(gemm_kernel, cudaFuncAttributeMaxDynamicSharedMemorySize,
                       GEMM_SMEM);
  cudaFuncSetAttribute(attn_mma_kernel, cudaFuncAttributeMaxDynamicSharedMemorySize,
                       ATTN_SMEM);

  cvt_kernel<<<(NTOK * DMODEL / 4 + 255) / 256, 256>>>(x, xh, NTOK * DMODEL / 4);
  wcvt_kernel<<<dim3((NH*HDIM)/32, DMODEL/32), dim3(32, 8)>>>(Wq, wqh, DMODEL, NH*HDIM);
  wcvt_kernel<<<dim3((NKV*HDIM)/32, DMODEL/32), dim3(32, 8)>>>(Wk, wkh, DMODEL, NKV*HDIM);
  wcvt_kernel<<<dim3((NKV*HDIM)/32, DMODEL/32), dim3(32, 8)>>>(Wv, wvh, DMODEL, NKV*HDIM);
  wcvt_kernel<<<dim3(DMODEL/32, DMODEL/32), dim3(32, 8)>>>(Wo, woh, DMODEL, DMODEL);

  gemm_kernel<<<dim3((NH*HDIM)/GBN, NTOK/GBM), 256, GEMM_SMEM>>>(
      xh, wqh, gq, nullptr, DMODEL, NH*HDIM);
  gemm_kernel<<<dim3((NKV*HDIM)/GBN, NTOK/GBM), 256, GEMM_SMEM>>>(
      xh, wkh, gk, nullptr, DMODEL, NKV*HDIM);
  gemm_kernel<<<dim3((NKV*HDIM)/GBN, NTOK/GBM), 256, GEMM_SMEM>>>(
      xh, wvh, nullptr, vbh, DMODEL, NKV*HDIM);

  rope_norm_kernel<<<dim3(NTOK, NH + NKV), 64>>>();

  attn_mma_kernel<<<dim3(SEQ / 16, NH, BATCH), 256, ATTN_SMEM>>>(attn, write_attn);

  gemm_kernel<<<dim3(DMODEL/GBN, NTOK/GBM), 256, GEMM_SMEM>>>(
      cth, woh, out, nullptr, DMODEL, DMODEL);
}

// round 16
// speedup vs baseline: 4.6124x; 1.2587x over previous
#include <cuda_runtime.h>
#include <cuda_fp16.h>
#include <math.h>
#include <stdint.h>

#define NH     16
#define NKV    4
#define HDIM   128
#define BATCH  2
#define SEQ    2048
#define DMODEL 2048
#define NTOK   (BATCH*SEQ)
#define NQKV   (DMODEL + 2*NKV*HDIM)   // 3072

// ---------------------------------------------------------------------------
// scratch
// ---------------------------------------------------------------------------
static __device__ float g_q[NTOK * NH * HDIM];
static __device__ float g_k[NTOK * NKV * HDIM];

static __device__ __half g_qh[NTOK * NH * HDIM];
static __device__ __half g_kbh[NTOK * NKV * HDIM];
static __device__ __half g_vbh[NTOK * NKV * HDIM];

static __device__ __half g_xh[NTOK * DMODEL];
static __device__ __half g_cth[NTOK * DMODEL];
static __device__ __half g_wqkv[NQKV * DMODEL];   // rows: [Wq 2048][Wk 512][Wv 512]
static __device__ __half g_woh[DMODEL * DMODEL];

// ---------------------------------------------------------------------------
// helpers
// ---------------------------------------------------------------------------
__device__ __forceinline__ uint32_t smem_u32(const void* p) {
  uint32_t a;
  asm("{ .reg .u64 t; cvta.to.shared.u64 t, %1; cvt.u32.u64 %0, t; }" : "=r"(a) : "l"(p));
  return a;
}

#define LDSM4(R, addr)                                                        \
  asm volatile("ldmatrix.sync.aligned.m8n8.x4.shared.b16 {%0,%1,%2,%3}, [%4];"\
    : "=r"((R)[0]), "=r"((R)[1]), "=r"((R)[2]), "=r"((R)[3]) : "r"(addr))

#define LDSM4T(R, addr)                                                       \
  asm volatile("ldmatrix.sync.aligned.m8n8.x4.trans.shared.b16 {%0,%1,%2,%3}, [%4];"\
    : "=r"((R)[0]), "=r"((R)[1]), "=r"((R)[2]), "=r"((R)[3]) : "r"(addr))

#define MMAF16(D, A, b0v, b1v)                                                \
  asm volatile("mma.sync.aligned.m16n8k16.row.col.f32.f16.f16.f32 "           \
    "{%0,%1,%2,%3}, {%4,%5,%6,%7}, {%8,%9}, {%0,%1,%2,%3};"                   \
    : "+f"((D)[0]), "+f"((D)[1]), "+f"((D)[2]), "+f"((D)[3])                  \
    : "r"((A)[0]), "r"((A)[1]), "r"((A)[2]), "r"((A)[3]), "r"(b0v), "r"(b1v))

#define CP_ASYNC16(dst, src) \
  asm volatile("cp.async.cg.shared.global [%0], [%1], 16;" :: "r"(dst), "l"(src))
#define CP_COMMIT() asm volatile("cp.async.commit_group;")

// ---------------------------------------------------------------------------
// fp32 -> fp16 convert
// ---------------------------------------------------------------------------
__global__ void __launch_bounds__(256) cvt_kernel(const float* __restrict__ src,
    __half* __restrict__ dst, int n4) {
  int i = blockIdx.x * 256 + threadIdx.x;
  if (i < n4) {
    float4 v = *(const float4*)(src + (size_t)i * 4);
    __half2 a, b;
    a.x = __float2half_rn(v.x); a.y = __float2half_rn(v.y);
    b.x = __float2half_rn(v.z); b.y = __float2half_rn(v.w);
    *(__half2*)(dst + (size_t)i * 4) = a;
    *(__half2*)(dst + (size_t)i * 4 + 2) = b;
  }
}

// W [K,N] fp32 -> transposed fp16 [N,K] at row offset
__global__ void __launch_bounds__(256) wcvt_kernel(const float* __restrict__ W,
    __half* __restrict__ th, int K, int N) {
  __shared__ float t[32][33];
  int n0 = blockIdx.x * 32, k0 = blockIdx.y * 32;
  int x = threadIdx.x, y = threadIdx.y;  // 32 x 8
  #pragma unroll
  for (int i = 0; i < 4; i++)
    t[y * 4 + i][x] = W[(size_t)(k0 + y * 4 + i) * N + n0 + x];
  __syncthreads();
  #pragma unroll
  for (int i = 0; i < 4; i++) {
    int n = n0 + y * 4 + i;
    th[(size_t)n * K + k0 + x] = __float2half_rn(t[x][y * 4 + i]);
  }
}

// ---------------------------------------------------------------------------
// GEMM core (pure fp16 operands, fp32 accum), 128x128 tile, BK=32, 2-stage.
// ---------------------------------------------------------------------------
#define GBM 128
#define GBN 128
#define GBK 32
#define RSTRIDE 80
#define TILE_BYTES (128 * RSTRIDE)
#define STG_BYTES (2 * TILE_BYTES)
#define GEMM_SMEM (2 * STG_BYTES)

struct GemmAcc { float a[2][8][4]; };

__device__ __forceinline__ void gemm_core(
    const __half* __restrict__ Ah, const __half* __restrict__ Bh,
    int bm, int bn, int K, uint32_t sbase, GemmAcc& acc) {
  int tid = threadIdx.x;
  int wid = tid >> 5, lane = tid & 31;
  int wm = wid >> 1, wn = wid & 1;
  int nc = K / GBK;

  auto load_chunk = [&](int c, int buf) {
    int k0 = c * GBK;
    #pragma unroll
    for (int i = 0; i < 4; i++) {
      int idx = tid + i * 256;
      int t = i >> 1;
      int r = (idx >> 2) & 127;
      int g = idx & 3;
      uint32_t dst = sbase + buf * STG_BYTES + t * TILE_BYTES + r * RSTRIDE + g * 16;
      const __half* src = (t ? Bh : Ah) + (size_t)((t ? bn : bm) + r) * K + k0 + g * 8;
      CP_ASYNC16(dst, src);
    }
    CP_COMMIT();
  };

  #pragma unroll
  for (int mi = 0; mi < 2; mi++)
    #pragma unroll
    for (int ni = 0; ni < 8; ni++)
      #pragma unroll
      for (int j = 0; j < 4; j++) acc.a[mi][ni][j] = 0.f;

  load_chunk(0, 0);
  int lrow = lane & 15, lk8 = (lane >> 4) * 8;

  for (int c = 0; c < nc; c++) {
    if (c + 1 < nc) {
      load_chunk(c + 1, (c + 1) & 1);
      asm volatile("cp.async.wait_group 1;");
    } else {
      asm volatile("cp.async.wait_group 0;");
    }
    __syncthreads();

    uint32_t b0 = sbase + (c & 1) * STG_BYTES;
    uint32_t aHs = b0, bHs = b0 + TILE_BYTES;

    #pragma unroll
    for (int kk = 0; kk < GBK; kk += 16) {
      uint32_t ah[2][4];
      uint32_t aoff = (uint32_t)(wm * 32 + lrow) * RSTRIDE + (kk + lk8) * 2;
      LDSM4(ah[0], aHs + aoff);
      LDSM4(ah[1], aHs + aoff + 16 * RSTRIDE);
      #pragma unroll
      for (int p = 0; p < 4; p++) {
        uint32_t boff = (uint32_t)(wn * 64 + p * 16 + lrow) * RSTRIDE + (kk + lk8) * 2;
        uint32_t h[4];
        LDSM4(h, bHs + boff);
        #pragma unroll
        for (int mi = 0; mi < 2; mi++) {
          MMAF16(acc.a[mi][2 * p],     ah[mi], h[0], h[2]);
          MMAF16(acc.a[mi][2 * p + 1], ah[mi], h[1], h[3]);
        }
      }
    }
    __syncthreads();
  }
}

// merged QKV projection: A = xh [NTOK, 2048], B = wqkv [3072, 2048].
// epilogue routes: cols [0,2048) -> g_q fp32; [2048,2560) -> g_k fp32;
// [2560,3072) -> g_vbh fp16.
__global__ void __launch_bounds__(256, 2) gemm_qkv_kernel(
    const __half* __restrict__ Ah, const __half* __restrict__ Bh) {
  extern __shared__ char smem[];
  uint32_t sbase = smem_u32(smem);
  int bm = blockIdx.y * GBM, bn = blockIdx.x * GBN;
  GemmAcc acc;
  gemm_core(Ah, Bh, bm, bn, DMODEL, sbase, acc);

  int wid = threadIdx.x >> 5, lane = threadIdx.x & 31;
  int wm = wid >> 1, wn = wid & 1;
  int gid = lane >> 2, cid = lane & 3;
  #pragma unroll
  for (int mi = 0; mi < 2; mi++)
    #pragma unroll
    for (int ni = 0; ni < 8; ni++) {
      int row = bm + wm * 32 + mi * 16 + gid;
      int col = bn + wn * 64 + ni * 8 + cid * 2;
      #pragma unroll
      for (int half = 0; half < 2; half++) {
        float v0 = acc.a[mi][ni][2 * half], v1 = acc.a[mi][ni][2 * half + 1];
        int rr = row + half * 8;
        if (col < DMODEL) {
          *(float2*)(g_q + (size_t)rr * DMODEL + col) = make_float2(v0, v1);
        } else if (col < DMODEL + 512) {
          *(float2*)(g_k + (size_t)rr * 512 + (col - DMODEL)) = make_float2(v0, v1);
        } else {
          __half2 hh;
          hh.x = __float2half_rn(v0);
          hh.y = __float2half_rn(v1);
          *(__half2*)(g_vbh + (size_t)rr * 512 + (col - DMODEL - 512)) = hh;
        }
      }
    }
}

// output projection: fp32 out
__global__ void __launch_bounds__(256, 2) gemm_out_kernel(
    const __half* __restrict__ Ah, const __half* __restrict__ Bh,
    float* __restrict__ Cf) {
  extern __shared__ char smem[];
  uint32_t sbase = smem_u32(smem);
  int bm = blockIdx.y * GBM, bn = blockIdx.x * GBN;
  GemmAcc acc;
  gemm_core(Ah, Bh, bm, bn, DMODEL, sbase, acc);

  int wid = threadIdx.x >> 5, lane = threadIdx.x & 31;
  int wm = wid >> 1, wn = wid & 1;
  int gid = lane >> 2, cid = lane & 3;
  #pragma unroll
  for (int mi = 0; mi < 2; mi++)
    #pragma unroll
    for (int ni = 0; ni < 8; ni++) {
      int row = bm + wm * 32 + mi * 16 + gid;
      int col = bn + wn * 64 + ni * 8 + cid * 2;
      *(float2*)(Cf + (size_t)row * DMODEL + col) =
          make_float2(acc.a[mi][ni][0], acc.a[mi][ni][1]);
      *(float2*)(Cf + (size_t)(row + 8) * DMODEL + col) =
          make_float2(acc.a[mi][ni][2], acc.a[mi][ni][3]);
    }
}

// ---------------------------------------------------------------------------
// RoPE + L2 norm: q/k -> fp16
// ---------------------------------------------------------------------------
__global__ void __launch_bounds__(64) rope_norm_kernel() {
  int tok = blockIdx.x;
  int r = blockIdx.y;
  size_t off = (r < NH) ? ((size_t)tok * NH + r) * HDIM
                        : ((size_t)tok * NKV + (r - NH)) * HDIM;
  const float* base = (r < NH) ? g_q + off : g_k + off;
  __half* dst = (r < NH) ? g_qh + off : g_kbh + off;
  int pos = tok & (SEQ - 1);
  int i = threadIdx.x;
  float t0 = base[2 * i], t1 = base[2 * i + 1];
  float inv = exp2f((float)(2 * i) * (-13.287712379549449f / 128.0f));
  float ang = (float)pos * inv;
  float sn, cs;
  sincosf(ang, &sn, &cs);
  float r0 = t0 * cs - t1 * sn;
  float r1 = t0 * sn + t1 * cs;
  float ss = r0 * r0 + r1 * r1;
  #pragma unroll
  for (int o = 16; o; o >>= 1) ss += __shfl_xor_sync(0xffffffffu, ss, o);
  __shared__ float part[2];
  if ((i & 31) == 0) part[i >> 5] = ss;
  __syncthreads();
  float sc = rsqrtf((part[0] + part[1]) * (1.0f / 128.0f) + 1e-6f);
  __half2 hh;
  hh.x = __float2half_rn(r0 * sc);
  hh.y = __float2half_rn(r1 * sc);
  *(__half2*)(dst + 2 * i) = hh;
}

// ---------------------------------------------------------------------------
// MMA attention: QK/AV 1-term fp16, cp.async double-buffered K/V staging,
// probs computed once and reused for AV.
// ---------------------------------------------------------------------------
#define SCW 2056
#define PAD_STR 272
#define OFF_QH 131584
#define OFF_K0 (OFF_QH + 16*PAD_STR)
#define OFF_K1 (OFF_K0 + 128*PAD_STR)
#define OFF_PH (OFF_K1 + 128*PAD_STR)
#define OFF_RED (OFF_PH + 16*PAD_STR)
#define ATTN_SMEM (OFF_RED + 128)

__global__ void __launch_bounds__(256, 1) attn_mma_kernel(
    float* __restrict__ attn_out, int write_attn) {
  extern __shared__ char smc[];
  float* s_scores = (float*)smc;
  float* s_red = (float*)(smc + OFF_RED);
  uint32_t sb = smem_u32(smc);

  int qb = gridDim.x - 1 - blockIdx.x;
  int h = blockIdx.y, b = blockIdx.z;
  int hk = h >> 2;
  int tid = threadIdx.x, w = tid >> 5, lane = tid & 31;
  int kend = qb * 16 + 16;
  int nch = (kend + 127) >> 7;
  const float SC = 0.08838834764831845f;
  int lrow = lane & 15, lhi = lane >> 4;
  uint32_t kbuf[2] = {sb + OFF_K0, sb + OFF_K1};

  // staging: unconditional (rows beyond kend read valid neighbor tokens;
  // masked by causal predicate / zero P downstream)
  auto load_kv = [&](const __half* srcbase, int kc, uint32_t dstbase) {
    #pragma unroll
    for (int i = 0; i < 8; i++) {
      int idx = tid + i * 256;
      int r = idx >> 4, g = idx & 15;
      const __half* src = srcbase + ((size_t)(b * SEQ + kc + r) * NKV + hk) * HDIM + g * 8;
      CP_ASYNC16(dstbase + r * PAD_STR + g * 16, src);
    }
    CP_COMMIT();
  };

  // Q tile
  {
    int r = tid >> 4, g = tid & 15;
    size_t go = ((size_t)(b * SEQ + qb * 16 + r) * NH + h) * HDIM + g * 8;
    *(uint4*)(smc + OFF_QH + r * PAD_STR + g * 16) = *(const uint4*)(g_qh + go);
  }
  load_kv(g_kbh, 0, kbuf[0]);
  __syncthreads();

  uint32_t aH[8][4];
  #pragma unroll
  for (int kk = 0; kk < 8; kk++) {
    uint32_t off = lrow * PAD_STR + kk * 32 + lhi * 16;
    LDSM4(aH[kk], sb + OFF_QH + off);
  }

  // ---- scores ----
  for (int ci = 0; ci < nch; ci++) {
    int kc = ci << 7;
    if (ci + 1 < nch) {
      load_kv(g_kbh, kc + 128, kbuf[(ci + 1) & 1]);
      asm volatile("cp.async.wait_group 1;");
    } else {
      asm volatile("cp.async.wait_group 0;");
    }
    __syncthreads();

    uint32_t kb = kbuf[ci & 1];
    float acc[2][4] = {{0, 0, 0, 0}, {0, 0, 0, 0}};
    int n0 = w * 16;
    #pragma unroll
    for (int kk = 0; kk < 8; kk++) {
      uint32_t off = (uint32_t)(n0 + lrow) * PAD_STR + kk * 32 + lhi * 16;
      uint32_t bh[4];
      LDSM4(bh, kb + off);
      MMAF16(acc[0], aH[kk], bh[0], bh[2]);
      MMAF16(acc[1], aH[kk], bh[1], bh[3]);
    }
    int r0 = lane >> 2, c0 = (lane & 3) * 2;
    int qs0 = qb * 16;
    #pragma unroll
    for (int nt = 0; nt < 2; nt++) {
      int col = kc + n0 + nt * 8 + c0;
      s_scores[r0 * SCW + col]           = (col     <= qs0 + r0)     ? acc[nt][0] * SC : -1e30f;
      s_scores[r0 * SCW + col + 1]       = (col + 1 <= qs0 + r0)     ? acc[nt][1] * SC : -1e30f;
      s_scores[(r0 + 8) * SCW + col]     = (col     <= qs0 + r0 + 8) ? acc[nt][2] * SC : -1e30f;
      s_scores[(r0 + 8) * SCW + col + 1] = (col + 1 <= qs0 + r0 + 8) ? acc[nt][3] * SC : -1e30f;
    }
    __syncthreads();
  }

  // ---- softmax stats ----
  {
    int qi = tid >> 4, r = tid & 15;
    float m = -1e30f;
    for (int j = r; j < kend; j += 16) m = fmaxf(m, s_scores[qi * SCW + j]);
    #pragma unroll
    for (int o = 8; o; o >>= 1) m = fmaxf(m, __shfl_xor_sync(0xffffffffu, m, o));
    float s = 0.f;
    for (int j = r; j < kend; j += 16) s += __expf(s_scores[qi * SCW + j] - m);
    #pragma unroll
    for (int o = 8; o; o >>= 1) s += __shfl_xor_sync(0xffffffffu, s, o);
    if (r == 0) { s_red[qi] = m; s_red[16 + qi] = 1.0f / s; }
  }
  __syncthreads();

  // ---- probs: normalize once (store into s_scores), optionally write out ----
  {
    float* ab = attn_out + ((size_t)(b * NH + h) * SEQ + (size_t)qb * 16) * SEQ;
    for (int idx = tid; idx < 16 * 512; idx += 256) {
      int qi = idx >> 9, j4 = (idx & 511) * 4;
      float m = s_red[qi], inv = s_red[16 + qi];
      float4 p = {0, 0, 0, 0};
      if (j4 < kend) {
        p.x = __expf(s_scores[qi * SCW + j4] - m) * inv;
        if (j4 + 1 < kend) p.y = __expf(s_scores[qi * SCW + j4 + 1] - m) * inv;
        if (j4 + 2 < kend) p.z = __expf(s_scores[qi * SCW + j4 + 2] - m) * inv;
        if (j4 + 3 < kend) p.w = __expf(s_scores[qi * SCW + j4 + 3] - m) * inv;
        s_scores[qi * SCW + j4]     = p.x;
        s_scores[qi * SCW + j4 + 1] = p.y;
        s_scores[qi * SCW + j4 + 2] = p.z;
        s_scores[qi * SCW + j4 + 3] = p.w;
      }
      if (write_attn) *(float4*)(ab + (size_t)qi * SEQ + j4) = p;
    }
  }
  __syncthreads();

  // ---- AV ----
  float oacc[2][4] = {{0, 0, 0, 0}, {0, 0, 0, 0}};
  load_kv(g_vbh, 0, kbuf[0]);
  for (int ci = 0; ci < nch; ci++) {
    int kc = ci << 7;
    if (ci + 1 < nch) load_kv(g_vbh, kc + 128, kbuf[(ci + 1) & 1]);
    // P staging (reads stored probs; no exp)
    for (int idx = tid; idx < 16 * 64; idx += 256) {
      int r = idx >> 6, c2 = (idx & 63) * 2;
      float p0 = (kc + c2 < kend)     ? s_scores[r * SCW + kc + c2]     : 0.f;
      float p1 = (kc + c2 + 1 < kend) ? s_scores[r * SCW + kc + c2 + 1] : 0.f;
      __half2 hh;
      hh.x = __float2half_rn(p0);
      hh.y = __float2half_rn(p1);
      *(__half2*)(smc + OFF_PH + r * PAD_STR + c2 * 2) = hh;
    }
    if (ci + 1 < nch) asm volatile("cp.async.wait_group 1;");
    else              asm volatile("cp.async.wait_group 0;");
    __syncthreads();

    uint32_t vb = kbuf[ci & 1];
    #pragma unroll
    for (int kk = 0; kk < 8; kk++) {
      uint32_t pOff = lrow * PAD_STR + kk * 32 + lhi * 16;
      uint32_t ph[4];
      LDSM4(ph, sb + OFF_PH + pOff);
      uint32_t vOff = (uint32_t)(kk * 16 + lrow) * PAD_STR + w * 32 + lhi * 16;
      uint32_t vh[4];
      LDSM4T(vh, vb + vOff);
      MMAF16(oacc[0], ph, vh[0], vh[1]);
      MMAF16(oacc[1], ph, vh[2], vh[3]);
    }
    __syncthreads();
  }

  // epilogue: ctx fp16 [tok, H*HD]
  {
    int r0 = lane >> 2, c0 = (lane & 3) * 2;
    #pragma unroll
    for (int nt = 0; nt < 2; nt++) {
      int col = w * 16 + nt * 8 + c0;
      #pragma unroll
      for (int half = 0; half < 2; half++) {
        __half2 hh;
        hh.x = __float2half_rn(oacc[nt][2 * half]);
        hh.y = __float2half_rn(oacc[nt][2 * half + 1]);
        size_t o = ((size_t)(b * SEQ + qb * 16 + r0 + half * 8)) * DMODEL
                 + h * HDIM + col;
        *(__half2*)(g_cth + o) = hh;
      }
    }
  }
}

// ---------------------------------------------------------------------------
extern "C" void kernel_launch(void* const* d_in, const int* in_sizes, int n_in,
                              void* d_out, int out_size) {
  const float* x  = (const float*)d_in[0];
  const float* Wq = (const float*)d_in[1];
  const float* Wk = (const float*)d_in[2];
  const float* Wv = (const float*)d_in[3];
  const float* Wo = (const float*)d_in[4];
  float* out = (float*)d_out;
  float* attn = out + (size_t)NTOK * DMODEL;
  long long need = (long long)NTOK * DMODEL + (long long)BATCH * NH * SEQ * SEQ;
  int write_attn = ((long long)out_size >= need) ? 1 : 0;

  __half *xh, *cth, *wqkv, *woh;
  cudaGetSymbolAddress((void**)&xh, g_xh);
  cudaGetSymbolAddress((void**)&cth, g_cth);
  cudaGetSymbolAddress((void**)&wqkv, g_wqkv);
  cudaGetSymbolAddress((void**)&woh, g_woh);

  cudaFuncSetAttribute(gemm_qkv_kernel, cudaFuncAttributeMaxDynamicSharedMemorySize,
                       GEMM_SMEM);
  cudaFuncSetAttribute(gemm_out_kernel, cudaFuncAttributeMaxDynamicSharedMemorySize,
                       GEMM_SMEM);
  cudaFuncSetAttribute(attn_mma_kernel, cudaFuncAttributeMaxDynamicSharedMemorySize,
                       ATTN_SMEM);

  cvt_kernel<<<(NTOK * DMODEL / 4 + 255) / 256, 256>>>(x, xh, NTOK * DMODEL / 4);
  // combined weights [Wq | Wk | Wv] transposed into one buffer
  wcvt_kernel<<<dim3((NH*HDIM)/32, DMODEL/32), dim3(32, 8)>>>(Wq, wqkv, DMODEL, NH*HDIM);
  wcvt_kernel<<<dim3((NKV*HDIM)/32, DMODEL/32), dim3(32, 8)>>>(
      Wk, wqkv + (size_t)DMODEL * DMODEL, DMODEL, NKV*HDIM);
  wcvt_kernel<<<dim3((NKV*HDIM)/32, DMODEL/32), dim3(32, 8)>>>(
      Wv, wqkv + (size_t)(DMODEL + 512) * DMODEL, DMODEL, NKV*HDIM);
  wcvt_kernel<<<dim3(DMODEL/32, DMODEL/32), dim3(32, 8)>>>(Wo, woh, DMODEL, DMODEL);

  // merged QKV projection
  gemm_qkv_kernel<<<dim3(NQKV/GBN, NTOK/GBM), 256, GEMM_SMEM>>>(xh, wqkv);

  rope_norm_kernel<<<dim3(NTOK, NH + NKV), 64>>>();

  attn_mma_kernel<<<dim3(SEQ / 16, NH, BATCH), 256, ATTN_SMEM>>>(attn, write_attn);

  gemm_out_kernel<<<dim3(DMODEL/GBN, NTOK/GBM), 256, GEMM_SMEM>>>(cth, woh, out);
}